// round 10
// baseline (speedup 1.0000x reference)
#include <cuda_runtime.h>
#include <cuda_bf16.h>
#include <cstdint>
#include <math.h>

// ---------------------------------------------------------------------------
// Problem constants
// ---------------------------------------------------------------------------
#define B_   2
#define L_   2521
#define C_   2048
#define H_   16
#define HD_  128
#define M_   (B_ * L_)          // 5042
#define K_   2048
#define KP_  1024               // K/2 u32 pairs per row
#define NQKV 6144

__device__ __constant__ int d_cum[10] = {1, 5, 21, 57, 121, 265, 521, 921, 1497, 2521};

// f32 scratch; q/k stored d-PERMUTED (perm8 within 8-groups) and tf32-rounded,
// v stored plain d-order, tf32-rounded.
__device__ float g_q[B_ * H_ * L_ * HD_];
__device__ float g_k[B_ * H_ * L_ * HD_];
__device__ float g_v[B_ * H_ * L_ * HD_];

// split-bf16 scratch (u32 = packed bf16x2, pair-permuted layout)
__device__ uint32_t g_xh[M_ * KP_],   g_xl[M_ * KP_];
__device__ uint32_t g_wh[NQKV * KP_], g_wl[NQKV * KP_];
__device__ uint32_t g_pwh[C_ * KP_],  g_pwl[C_ * KP_];
__device__ uint32_t g_aoh[M_ * KP_],  g_aol[M_ * KP_];

// ---------------------------------------------------------------------------
// helpers
// ---------------------------------------------------------------------------
__device__ __forceinline__ uint32_t f2tf(float x) {
    uint32_t r;
    asm("cvt.rna.tf32.f32 %0, %1;" : "=r"(r) : "f"(x));
    return r;
}
__device__ __forceinline__ float tf32r(float x) { return __uint_as_float(f2tf(x)); }

__device__ __forceinline__ void mma8(float* c,
                                     uint32_t a0, uint32_t a1, uint32_t a2, uint32_t a3,
                                     uint32_t b0, uint32_t b1)
{
    asm volatile(
        "mma.sync.aligned.m16n8k8.row.col.f32.tf32.tf32.f32 "
        "{%0,%1,%2,%3}, {%4,%5,%6,%7}, {%8,%9}, {%0,%1,%2,%3};"
        : "+f"(c[0]), "+f"(c[1]), "+f"(c[2]), "+f"(c[3])
        : "r"(a0), "r"(a1), "r"(a2), "r"(a3), "r"(b0), "r"(b1));
}

__device__ __forceinline__ void mma16(float* c,
                                      uint32_t a0, uint32_t a1, uint32_t a2, uint32_t a3,
                                      uint32_t b0, uint32_t b1)
{
    asm volatile(
        "mma.sync.aligned.m16n8k16.row.col.f32.bf16.bf16.f32 "
        "{%0,%1,%2,%3}, {%4,%5,%6,%7}, {%8,%9}, {%0,%1,%2,%3};"
        : "+f"(c[0]), "+f"(c[1]), "+f"(c[2]), "+f"(c[3])
        : "r"(a0), "r"(a1), "r"(a2), "r"(a3), "r"(b0), "r"(b1));
}

__device__ __forceinline__ uint32_t smaddr(const void* p) {
    return (uint32_t)__cvta_generic_to_shared(p);
}
__device__ __forceinline__ void cp16(uint32_t dst, const void* src, bool pred) {
    int sz = pred ? 16 : 0;
    asm volatile("cp.async.cg.shared.global [%0], [%1], 16, %2;"
                 :: "r"(dst), "l"(src), "r"(sz));
}
__device__ __forceinline__ void cp_commit() {
    asm volatile("cp.async.commit_group;");
}
template<int N>
__device__ __forceinline__ void cp_wait() {
    asm volatile("cp.async.wait_group %0;" :: "n"(N));
}

// permuted pair column for split-bf16 GEMM fragments
__device__ __forceinline__ int pair_perm(int p) {
    int q = p & 15;
    return (p & ~15) + (q & 8) + (q & 3) * 2 + ((q >> 2) & 1);
}

__device__ __forceinline__ void split_pack(float x0, float x1, uint32_t& hp, uint32_t& lp) {
    __nv_bfloat16 h0 = __float2bfloat16_rn(x0);
    __nv_bfloat16 h1 = __float2bfloat16_rn(x1);
    float l0f = x0 - __bfloat162float(h0);
    float l1f = x1 - __bfloat162float(h1);
    __nv_bfloat16 l0 = __float2bfloat16_rn(l0f);
    __nv_bfloat16 l1 = __float2bfloat16_rn(l1f);
    hp = (uint32_t)__bfloat16_as_ushort(h0) | ((uint32_t)__bfloat16_as_ushort(h1) << 16);
    lp = (uint32_t)__bfloat16_as_ushort(l0) | ((uint32_t)__bfloat16_as_ushort(l1) << 16);
}

// ---------------------------------------------------------------------------
// Kernel 0: f32 -> split-bf16 pre-conversion (permuted layout)
// ---------------------------------------------------------------------------
__global__ void __launch_bounds__(256)
convert_split(const float* __restrict__ src, int which, int npairs)
{
    int i = blockIdx.x * 256 + threadIdx.x;
    if (i >= npairs) return;
    int row = i >> 10;
    int p = i & 1023;
    float2 v = *(const float2*)(src + (size_t)row * K_ + p * 2);
    uint32_t hp, lp;
    split_pack(v.x, v.y, hp, lp);
    int c = pair_perm(p);
    uint32_t* hi = (which == 0) ? g_xh : (which == 1) ? g_wh : g_pwh;
    uint32_t* lo = (which == 0) ? g_xl : (which == 1) ? g_wl : g_pwl;
    hi[(size_t)row * KP_ + c] = hp;
    lo[(size_t)row * KP_ + c] = lp;
}

// ---------------------------------------------------------------------------
// GEMM core (R6 config): split-bf16, cp.async 3-stage, BK=32, XOR swizzle.
// Block 128x128, 8 warps = 4m x 2n, warp tile 32x64. 2 CTAs/SM.
// ---------------------------------------------------------------------------
#define GW 16
#define GARR (128 * GW)          // 2048 u32
#define GSTAGE (4 * GARR)        // 8192 u32 = 32 KB

__device__ __forceinline__ void gemm_prefetch(
    uint32_t* sbase, const uint32_t* agh, const uint32_t* agl,
    const uint32_t* bgh, const uint32_t* bgl, int ku, bool aok, int r, int fq)
{
    int sw = (r & 3) << 2;
    int w0 = ((fq ^ sw)) * 4;
    int w1 = (((fq + 4) ^ sw)) * 4;
    uint32_t dA = smaddr(sbase + r * GW);
    cp16(dA + w0, agh + ku,     aok);
    cp16(dA + w1, agh + ku + 4, aok);
    uint32_t dAl = dA + GARR * 4;
    cp16(dAl + w0, agl + ku,     aok);
    cp16(dAl + w1, agl + ku + 4, aok);
    uint32_t dB = dAl + GARR * 4;
    cp16(dB + w0, bgh + ku,     true);
    cp16(dB + w1, bgh + ku + 4, true);
    uint32_t dBl = dB + GARR * 4;
    cp16(dBl + w0, bgl + ku,     true);
    cp16(dBl + w1, bgl + ku + 4, true);
}

__device__ __forceinline__ void gemm_core_bf16s(
    const uint32_t* __restrict__ Ahg, const uint32_t* __restrict__ Alg,
    const uint32_t* __restrict__ Bhg, const uint32_t* __restrict__ Blg,
    int m0, int n0, uint32_t* sm, float acc[2][8][4], int tid)
{
    const int lane = tid & 31, wid = tid >> 5;
    const int g = lane >> 2, t = lane & 3;
    const int mw = (wid >> 1) * 32, nw = (wid & 1) * 64;

    const int r = tid >> 1;
    const int fq = (tid & 1) * 8;
    const bool aok = (m0 + r) < M_;
    const int arow = aok ? (m0 + r) : 0;
    const uint32_t* agh = Ahg + (size_t)arow * KP_ + fq;
    const uint32_t* agl = Alg + (size_t)arow * KP_ + fq;
    const uint32_t* bgh = Bhg + (size_t)(n0 + r) * KP_ + fq;
    const uint32_t* bgl = Blg + (size_t)(n0 + r) * KP_ + fq;

    gemm_prefetch(sm,              agh, agl, bgh, bgl, 0,  aok, r, fq);
    cp_commit();
    gemm_prefetch(sm + GSTAGE,     agh, agl, bgh, bgl, 16, aok, r, fq);
    cp_commit();

    const int swf = (g & 3) << 2;
    const int NIT = KP_ / 16;    // 64

    for (int it = 0; it < NIT; it++) {
        if (it + 1 >= NIT) cp_wait<0>(); else cp_wait<1>();
        __syncthreads();
        if (it + 2 < NIT) {
            gemm_prefetch(sm + ((it + 2) % 3) * GSTAGE, agh, agl, bgh, bgl,
                          (it + 2) * 16, aok, r, fq);
            cp_commit();
        }

        uint32_t* Ah = sm + (it % 3) * GSTAGE;
        uint32_t* Al = Ah + GARR;
        uint32_t* Bh = Al + GARR;
        uint32_t* Bl = Bh + GARR;

#pragma unroll
        for (int ks = 0; ks < 2; ks++) {
            const int wb = (ks * 8 + 2 * t) ^ swf;
            uint32_t ah[2][4], al[2][4];
#pragma unroll
            for (int mi = 0; mi < 2; mi++) {
                int r0 = mw + 16 * mi + g;
                uint2 v0 = *(uint2*)&Ah[r0 * GW + wb];
                uint2 v1 = *(uint2*)&Ah[(r0 + 8) * GW + wb];
                ah[mi][0] = v0.x; ah[mi][2] = v0.y;
                ah[mi][1] = v1.x; ah[mi][3] = v1.y;
                uint2 w0 = *(uint2*)&Al[r0 * GW + wb];
                uint2 w1 = *(uint2*)&Al[(r0 + 8) * GW + wb];
                al[mi][0] = w0.x; al[mi][2] = w0.y;
                al[mi][1] = w1.x; al[mi][3] = w1.y;
            }
#pragma unroll
            for (int j = 0; j < 8; j++) {
                int cn = nw + 8 * j + g;
                uint2 bh = *(uint2*)&Bh[cn * GW + wb];
                uint2 bl = *(uint2*)&Bl[cn * GW + wb];
#pragma unroll
                for (int mi = 0; mi < 2; mi++) {
                    mma16(acc[mi][j], ah[mi][0], ah[mi][1], ah[mi][2], ah[mi][3], bh.x, bh.y);
                    mma16(acc[mi][j], ah[mi][0], ah[mi][1], ah[mi][2], ah[mi][3], bl.x, bl.y);
                    mma16(acc[mi][j], al[mi][0], al[mi][1], al[mi][2], al[mi][3], bh.x, bh.y);
                }
            }
        }
    }
}

// ---------------------------------------------------------------------------
// Kernel 1: QKV GEMM + scatter epilogue (R6 version).
// ---------------------------------------------------------------------------
__global__ void __launch_bounds__(256, 2)
qkv_gemm(const float* __restrict__ qb, const float* __restrict__ vb)
{
    extern __shared__ uint32_t smu[];
    float acc[2][8][4];
#pragma unroll
    for (int a = 0; a < 2; a++)
#pragma unroll
        for (int b = 0; b < 8; b++)
#pragma unroll
            for (int c = 0; c < 4; c++) acc[a][b][c] = 0.f;

    const int n0 = blockIdx.x * 128;
    const int m0 = blockIdx.y * 128;
    gemm_core_bf16s(g_xh, g_xl, g_wh, g_wl, m0, n0, smu, acc, threadIdx.x);

    const int lane = threadIdx.x & 31, wid = threadIdx.x >> 5;
    const int g = lane >> 2, t = lane & 3;
    const int mw = (wid >> 1) * 32, nw = (wid & 1) * 64;

    const int tq = n0 >> 11;
    const int h = (n0 & 2047) >> 7;
    float* dst = (tq == 0) ? g_q : ((tq == 1) ? g_k : g_v);

    float2 bias[8];
#pragma unroll
    for (int j = 0; j < 8; j++) {
        int d = nw + 8 * j + 2 * t;
        float b0 = 0.f, b1 = 0.f;
        if (tq == 0) { b0 = qb[h * HD_ + d]; b1 = qb[h * HD_ + d + 1]; }
        else if (tq == 2) { b0 = vb[h * HD_ + d]; b1 = vb[h * HD_ + d + 1]; }
        bias[j] = make_float2(b0, b1);
    }

    const int sl0 = 4 * (t & 1) + (t >> 1);   // perm8(2t); perm8(2t+1) = sl0+2

#pragma unroll
    for (int mi = 0; mi < 2; mi++)
#pragma unroll
        for (int rr = 0; rr < 2; rr++) {
            int gm = m0 + mw + 16 * mi + g + 8 * rr;
            if (gm >= M_) continue;
            int b = gm / L_;
            int l = gm - b * L_;
            float* p = dst + ((size_t)(b * H_ + h) * L_ + l) * HD_;
#pragma unroll
            for (int j = 0; j < 8; j++) {
                float ox = acc[mi][j][2 * rr] + bias[j].x;
                float oy = acc[mi][j][2 * rr + 1] + bias[j].y;
                if (tq == 2) {
                    float2 o = make_float2(tf32r(ox), tf32r(oy));
                    *(float2*)(p + nw + 8 * j + 2 * t) = o;
                } else {
                    int dg = nw + 8 * j;
                    p[dg + sl0]     = ox;
                    p[dg + sl0 + 2] = oy;
                }
            }
        }
}

// ---------------------------------------------------------------------------
// Kernel 2: norm + rope on PERMUTED q/k storage; outputs tf32-rounded.
// ---------------------------------------------------------------------------
__global__ void __launch_bounds__(256)
norm_rope(const float* __restrict__ sml, const float* __restrict__ rope)
{
    const int gw = blockIdx.x * 8 + (threadIdx.x >> 5);
    const int lane = threadIdx.x & 31;
    if (gw >= B_ * H_ * L_) return;
    const int l = gw % L_;
    const int h = (gw / L_) % H_;

    float2 cc = *(const float2*)(rope + (size_t)l * 64 + lane * 2);
    float2 ss = *(const float2*)(rope + (size_t)L_ * 64 + (size_t)l * 64 + lane * 2);
    const float scale = __expf(fminf(sml[h], 4.605170185988091f));
    const size_t base = (size_t)gw * HD_ + (lane >> 1) * 8 + (lane & 1);

    {
        float v0 = g_q[base], v1 = g_q[base + 2], v2 = g_q[base + 4], v3 = g_q[base + 6];
        float ssq = v0 * v0 + v1 * v1 + v2 * v2 + v3 * v3;
#pragma unroll
        for (int o = 16; o; o >>= 1) ssq += __shfl_xor_sync(0xffffffffu, ssq, o);
        float inv = scale / fmaxf(sqrtf(ssq), 1e-12f);
        v0 *= inv; v1 *= inv; v2 *= inv; v3 *= inv;
        g_q[base]     = tf32r(cc.x * v0 - ss.x * v1);
        g_q[base + 2] = tf32r(ss.x * v0 + cc.x * v1);
        g_q[base + 4] = tf32r(cc.y * v2 - ss.y * v3);
        g_q[base + 6] = tf32r(ss.y * v2 + cc.y * v3);
    }
    {
        float v0 = g_k[base], v1 = g_k[base + 2], v2 = g_k[base + 4], v3 = g_k[base + 6];
        float ssq = v0 * v0 + v1 * v1 + v2 * v2 + v3 * v3;
#pragma unroll
        for (int o = 16; o; o >>= 1) ssq += __shfl_xor_sync(0xffffffffu, ssq, o);
        float inv = 1.f / fmaxf(sqrtf(ssq), 1e-12f);
        v0 *= inv; v1 *= inv; v2 *= inv; v3 *= inv;
        g_k[base]     = tf32r(cc.x * v0 - ss.x * v1);
        g_k[base + 2] = tf32r(ss.x * v0 + cc.x * v1);
        g_k[base + 4] = tf32r(cc.y * v2 - ss.y * v3);
        g_k[base + 6] = tf32r(ss.y * v2 + cc.y * v3);
    }
}

// ---------------------------------------------------------------------------
// Kernel 3: flash attention — 320 threads (10 warps), q-tile 160.
// Q staged into stages 1-2 while tile0 prefetches into stage0.
// Tile i lives in stage i%3. Numerics identical to R6 per row.
// ---------------------------------------------------------------------------
#define FW 128
#define FKB (64 * FW)
#define FSTG (2 * FKB)           // 64 KB per K+V stage
#define QT_ 160

__device__ __forceinline__ int kend_of(int lq) {
    if (lq >= L_) return 0;
    int ke = 2521;
#pragma unroll
    for (int i = 9; i >= 0; i--)
        if (lq < d_cum[i]) ke = d_cum[i];
    return ke;
}

__device__ __forceinline__ void flash_prefetch(
    float* sm, int s, int k0, const float* kp, const float* vp, int tid)
{
    if (tid >= 256) return;
    float* Kb = sm + s * FSTG;
    float* Vb = Kb + FKB;
    int kr = tid >> 2;
    int cb = (tid & 3) * 32;
    bool ok = (k0 + kr) < L_;
    const float* ks = kp + (size_t)(ok ? (k0 + kr) : 0) * HD_ + cb;
    int swk = (kr & 3) << 3;
    uint32_t dK = smaddr(Kb + kr * FW);
#pragma unroll
    for (int i = 0; i < 8; i++)
        cp16(dK + 4 * ((cb + 4 * i) ^ swk), ks + 4 * i, ok);
    int w = kr & 7;
    int slot = (kr & ~7) + (w >> 1) + ((w & 1) << 2);
    int swv = (slot & 3) << 3;
    const float* vs = vp + (size_t)(ok ? (k0 + kr) : 0) * HD_ + cb;
    uint32_t dV = smaddr(Vb + slot * FW);
#pragma unroll
    for (int i = 0; i < 8; i++)
        cp16(dV + 4 * ((cb + 4 * i) ^ swv), vs + 4 * i, ok);
}

__global__ void __launch_bounds__(320, 1)
flash_attn()
{
    extern __shared__ float sm[];

    const int bh = blockIdx.y;
    const int q0 = (gridDim.x - 1 - blockIdx.x) * QT_;
    const float* qp = g_q + (size_t)bh * L_ * HD_;
    const float* kp = g_k + (size_t)bh * L_ * HD_;
    const float* vp = g_v + (size_t)bh * L_ * HD_;
    const int tid = threadIdx.x, lane = tid & 31, wid = tid >> 5;
    const int g = lane >> 2, t = lane & 3;
    const int rowbase = wid * 16 + g;          // wid 0..9 -> rows 0..159
    const int swg = (g & 3) << 3;

    int kmax;
    {
        int lql = min(q0 + QT_ - 1, L_ - 1);
        kmax = 2521;
#pragma unroll
        for (int i = 9; i >= 0; i--)
            if (lql < d_cum[i]) kmax = d_cum[i];
    }
    const int niter = (kmax + 63) / 64;

    // stage Q (160 rows) into stages 1-2 region at sm + FSTG
    {
        int r = tid >> 1;                       // 0..159
        int cb = (tid & 1) * 64;
        bool ok = (q0 + r) < L_;
        const float* src = qp + (size_t)(ok ? (q0 + r) : 0) * HD_ + cb;
        int sw = (r & 3) << 3;
        uint32_t d = smaddr(sm + FSTG + r * FW);
#pragma unroll
        for (int i = 0; i < 16; i++)
            cp16(d + 4 * ((cb + 4 * i) ^ sw), src + 4 * i, ok);
    }
    cp_commit();
    // tile0 -> stage0 (doesn't overlap Q region)
    flash_prefetch(sm, 0, 0, kp, vp, tid);
    cp_commit();

    cp_wait<1>();        // Q landed; tile0 may still be in flight
    __syncthreads();

    uint32_t qf[16][4];
#pragma unroll
    for (int kk8 = 0; kk8 < 16; kk8++) {
        int wb = (kk8 * 8 + 2 * t) ^ swg;
        uint2 a0 = *(const uint2*)&sm[FSTG + rowbase * FW + wb];
        uint2 a1 = *(const uint2*)&sm[FSTG + (rowbase + 8) * FW + wb];
        qf[kk8][0] = a0.x; qf[kk8][2] = a0.y;
        qf[kk8][1] = a1.x; qf[kk8][3] = a1.y;
    }
    __syncthreads();

    if (niter > 1) {
        flash_prefetch(sm, 1, 64, kp, vp, tid);
        cp_commit();
    }

    const int kend0 = kend_of(q0 + rowbase);
    const int kend1 = kend_of(q0 + rowbase + 8);

    float m0v = -1e30f, m1v = -1e30f, l0v = 0.f, l1v = 0.f;
    float O[16][4];
#pragma unroll
    for (int j = 0; j < 16; j++)
#pragma unroll
        for (int c = 0; c < 4; c++) O[j][c] = 0.f;

    for (int it = 0; it < niter; it++) {
        const int k0 = it * 64;
        if (it + 1 >= niter) cp_wait<0>(); else cp_wait<1>();
        __syncthreads();
        if (it + 2 < niter) {
            flash_prefetch(sm, (it + 2) % 3, (it + 2) * 64, kp, vp, tid);
            cp_commit();
        }

        float* Kb = sm + (it % 3) * FSTG;
        float* Vb = Kb + FKB;

        float sc[8][4];
#pragma unroll
        for (int j = 0; j < 8; j++)
#pragma unroll
            for (int c = 0; c < 4; c++) sc[j][c] = 0.f;

#pragma unroll
        for (int kk8 = 0; kk8 < 16; kk8++) {
            int wb = (kk8 * 8 + 2 * t) ^ swg;
#pragma unroll
            for (int j = 0; j < 8; j++) {
                uint2 bb = *(const uint2*)&Kb[(8 * j + g) * FW + wb];
                mma8(sc[j], qf[kk8][0], qf[kk8][1], qf[kk8][2], qf[kk8][3], bb.x, bb.y);
            }
        }

        float rmax0 = -1e30f, rmax1 = -1e30f;
#pragma unroll
        for (int j = 0; j < 8; j++) {
            int c0 = k0 + 8 * j + 2 * t, c1 = c0 + 1;
            if (c0 >= kend0) sc[j][0] = -1e30f;
            if (c1 >= kend0) sc[j][1] = -1e30f;
            if (c0 >= kend1) sc[j][2] = -1e30f;
            if (c1 >= kend1) sc[j][3] = -1e30f;
            rmax0 = fmaxf(rmax0, fmaxf(sc[j][0], sc[j][1]));
            rmax1 = fmaxf(rmax1, fmaxf(sc[j][2], sc[j][3]));
        }
        rmax0 = fmaxf(rmax0, __shfl_xor_sync(0xffffffffu, rmax0, 1));
        rmax0 = fmaxf(rmax0, __shfl_xor_sync(0xffffffffu, rmax0, 2));
        rmax1 = fmaxf(rmax1, __shfl_xor_sync(0xffffffffu, rmax1, 1));
        rmax1 = fmaxf(rmax1, __shfl_xor_sync(0xffffffffu, rmax1, 2));

        float mn0 = fmaxf(m0v, rmax0), mn1 = fmaxf(m1v, rmax1);
        float al0 = __expf(m0v - mn0), al1 = __expf(m1v - mn1);
        float rs0 = 0.f, rs1 = 0.f;
#pragma unroll
        for (int j = 0; j < 8; j++) {
            float p0 = (sc[j][0] > -5e29f) ? __expf(sc[j][0] - mn0) : 0.f;
            float p1 = (sc[j][1] > -5e29f) ? __expf(sc[j][1] - mn0) : 0.f;
            float p2 = (sc[j][2] > -5e29f) ? __expf(sc[j][2] - mn1) : 0.f;
            float p3 = (sc[j][3] > -5e29f) ? __expf(sc[j][3] - mn1) : 0.f;
            rs0 += p0 + p1;
            rs1 += p2 + p3;
            sc[j][0] = p0; sc[j][1] = p1; sc[j][2] = p2; sc[j][3] = p3;
        }
        rs0 += __shfl_xor_sync(0xffffffffu, rs0, 1);
        rs0 += __shfl_xor_sync(0xffffffffu, rs0, 2);
        rs1 += __shfl_xor_sync(0xffffffffu, rs1, 1);
        rs1 += __shfl_xor_sync(0xffffffffu, rs1, 2);
        l0v = l0v * al0 + rs0;
        l1v = l1v * al1 + rs1;
        m0v = mn0; m1v = mn1;

#pragma unroll
        for (int j = 0; j < 16; j++) {
            O[j][0] *= al0; O[j][1] *= al0;
            O[j][2] *= al1; O[j][3] *= al1;
        }

        const int swv = t << 3;
#pragma unroll
        for (int c = 0; c < 8; c++) {
            uint32_t a0 = f2tf(sc[c][0]);
            uint32_t a1 = f2tf(sc[c][2]);
            uint32_t a2 = f2tf(sc[c][1]);
            uint32_t a3 = f2tf(sc[c][3]);
            const float* v0 = Vb + (8 * c + t) * FW;
            const float* v1 = Vb + (8 * c + t + 4) * FW;
#pragma unroll
            for (int j = 0; j < 16; j++) {
                int wv = (g + 8 * j) ^ swv;
                uint32_t b0 = __float_as_uint(v0[wv]);
                uint32_t b1 = __float_as_uint(v1[wv]);
                mma8(O[j], a0, a1, a2, a3, b0, b1);
            }
        }
    }

    // epilogue: normalize, convert to split-bf16 pairs, write permuted layout
    const int b = bh >> 4;
    const int h = bh & 15;
#pragma unroll
    for (int rr = 0; rr < 2; rr++) {
        int lq = q0 + rowbase + 8 * rr;
        if (lq >= L_) continue;
        float inv = 1.f / (rr ? l1v : l0v);
        size_t rowoff = (size_t)(b * L_ + lq) * KP_;
#pragma unroll
        for (int j = 0; j < 16; j++) {
            float x0 = O[j][2 * rr] * inv;
            float x1 = O[j][2 * rr + 1] * inv;
            uint32_t hp, lp;
            split_pack(x0, x1, hp, lp);
            int p = h * 64 + 4 * j + t;
            int c = pair_perm(p);
            g_aoh[rowoff + c] = hp;
            g_aol[rowoff + c] = lp;
        }
    }
}

// ---------------------------------------------------------------------------
// Kernel 4: projection GEMM (R6 version)
// ---------------------------------------------------------------------------
__global__ void __launch_bounds__(256, 2)
proj_gemm(const float* __restrict__ pb, float* __restrict__ out)
{
    extern __shared__ uint32_t smu[];
    float acc[2][8][4];
#pragma unroll
    for (int a = 0; a < 2; a++)
#pragma unroll
        for (int b = 0; b < 8; b++)
#pragma unroll
            for (int c = 0; c < 4; c++) acc[a][b][c] = 0.f;

    const int n0 = blockIdx.x * 128;
    const int m0 = blockIdx.y * 128;
    gemm_core_bf16s(g_aoh, g_aol, g_pwh, g_pwl, m0, n0, smu, acc, threadIdx.x);

    const int lane = threadIdx.x & 31, wid = threadIdx.x >> 5;
    const int g = lane >> 2, t = lane & 3;
    const int mw = (wid >> 1) * 32, nw = (wid & 1) * 64;

    float2 bias[8];
#pragma unroll
    for (int j = 0; j < 8; j++) {
        int n = n0 + nw + 8 * j + 2 * t;
        bias[j] = make_float2(pb[n], pb[n + 1]);
    }

#pragma unroll
    for (int mi = 0; mi < 2; mi++)
#pragma unroll
        for (int rr = 0; rr < 2; rr++) {
            int gm = m0 + mw + 16 * mi + g + 8 * rr;
            if (gm >= M_) continue;
            float* p = out + (size_t)gm * C_ + n0 + nw;
#pragma unroll
            for (int j = 0; j < 8; j++) {
                float2 o;
                o.x = acc[mi][j][2 * rr] + bias[j].x;
                o.y = acc[mi][j][2 * rr + 1] + bias[j].y;
                *(float2*)(p + 8 * j + 2 * t) = o;
            }
        }
}

// ---------------------------------------------------------------------------
// launch
// ---------------------------------------------------------------------------
extern "C" void kernel_launch(void* const* d_in, const int* in_sizes, int n_in,
                              void* d_out, int out_size)
{
    const float* x    = (const float*)d_in[0];
    const float* Wqkv = (const float*)d_in[1];
    const float* qb   = (const float*)d_in[2];
    const float* vb   = (const float*)d_in[3];
    const float* sml  = (const float*)d_in[4];
    const float* pW   = (const float*)d_in[5];
    const float* pb   = (const float*)d_in[6];
    const float* rope = (const float*)d_in[7];
    float* out = (float*)d_out;

    const size_t gemm_shm  = (size_t)3 * GSTAGE * sizeof(uint32_t);   // 98,304 B
    const size_t flash_shm = (size_t)3 * FSTG * sizeof(float);        // 196,608 B

    cudaFuncSetAttribute(qkv_gemm, cudaFuncAttributeMaxDynamicSharedMemorySize, (int)gemm_shm);
    cudaFuncSetAttribute(proj_gemm, cudaFuncAttributeMaxDynamicSharedMemorySize, (int)gemm_shm);
    cudaFuncSetAttribute(flash_attn, cudaFuncAttributeMaxDynamicSharedMemorySize, (int)flash_shm);

    {
        int np;
        np = M_ * KP_;    convert_split<<<(np + 255) / 256, 256>>>(x, 0, np);
        np = NQKV * KP_;  convert_split<<<(np + 255) / 256, 256>>>(Wqkv, 1, np);
        np = C_ * KP_;    convert_split<<<(np + 255) / 256, 256>>>(pW, 2, np);
    }

    dim3 g1(NQKV / 128, (M_ + 127) / 128);   // 48 x 40
    qkv_gemm<<<g1, 256, gemm_shm>>>(qb, vb);

    int nwarps = B_ * H_ * L_;
    norm_rope<<<(nwarps + 7) / 8, 256>>>(sml, rope);

    dim3 g3((L_ + QT_ - 1) / QT_, B_ * H_);  // 16 x 32
    flash_attn<<<g3, 320, flash_shm>>>();

    dim3 g4(C_ / 128, (M_ + 127) / 128);     // 16 x 40
    proj_gemm<<<g4, 256, gemm_shm>>>(pb, out);
}

// round 11
// speedup vs baseline: 1.6209x; 1.6209x over previous
#include <cuda_runtime.h>
#include <cuda_bf16.h>
#include <cstdint>
#include <math.h>

// ---------------------------------------------------------------------------
// Problem constants
// ---------------------------------------------------------------------------
#define B_   2
#define L_   2521
#define C_   2048
#define H_   16
#define HD_  128
#define M_   (B_ * L_)          // 5042
#define K_   2048
#define KP_  1024               // K/2 u32 pairs per row
#define NQKV 6144

__device__ __constant__ int d_cum[10] = {1, 5, 21, 57, 121, 265, 521, 921, 1497, 2521};

// f32 scratch; q/k stored d-PERMUTED (perm8 within 8-groups) and tf32-rounded,
// v stored plain d-order, tf32-rounded.
__device__ float g_q[B_ * H_ * L_ * HD_];
__device__ float g_k[B_ * H_ * L_ * HD_];
__device__ float g_v[B_ * H_ * L_ * HD_];

// split-bf16 scratch (u32 = packed bf16x2, pair-permuted layout)
__device__ uint32_t g_xh[M_ * KP_],   g_xl[M_ * KP_];
__device__ uint32_t g_wh[NQKV * KP_], g_wl[NQKV * KP_];
__device__ uint32_t g_pwh[C_ * KP_],  g_pwl[C_ * KP_];
__device__ uint32_t g_aoh[M_ * KP_],  g_aol[M_ * KP_];

// ---------------------------------------------------------------------------
// helpers
// ---------------------------------------------------------------------------
__device__ __forceinline__ uint32_t f2tf(float x) {
    uint32_t r;
    asm("cvt.rna.tf32.f32 %0, %1;" : "=r"(r) : "f"(x));
    return r;
}
__device__ __forceinline__ float tf32r(float x) { return __uint_as_float(f2tf(x)); }

__device__ __forceinline__ void mma8(float* c,
                                     uint32_t a0, uint32_t a1, uint32_t a2, uint32_t a3,
                                     uint32_t b0, uint32_t b1)
{
    asm volatile(
        "mma.sync.aligned.m16n8k8.row.col.f32.tf32.tf32.f32 "
        "{%0,%1,%2,%3}, {%4,%5,%6,%7}, {%8,%9}, {%0,%1,%2,%3};"
        : "+f"(c[0]), "+f"(c[1]), "+f"(c[2]), "+f"(c[3])
        : "r"(a0), "r"(a1), "r"(a2), "r"(a3), "r"(b0), "r"(b1));
}

__device__ __forceinline__ void mma16(float* c,
                                      uint32_t a0, uint32_t a1, uint32_t a2, uint32_t a3,
                                      uint32_t b0, uint32_t b1)
{
    asm volatile(
        "mma.sync.aligned.m16n8k16.row.col.f32.bf16.bf16.f32 "
        "{%0,%1,%2,%3}, {%4,%5,%6,%7}, {%8,%9}, {%0,%1,%2,%3};"
        : "+f"(c[0]), "+f"(c[1]), "+f"(c[2]), "+f"(c[3])
        : "r"(a0), "r"(a1), "r"(a2), "r"(a3), "r"(b0), "r"(b1));
}

__device__ __forceinline__ uint32_t smaddr(const void* p) {
    return (uint32_t)__cvta_generic_to_shared(p);
}
__device__ __forceinline__ void cp16(uint32_t dst, const void* src, bool pred) {
    int sz = pred ? 16 : 0;
    asm volatile("cp.async.cg.shared.global [%0], [%1], 16, %2;"
                 :: "r"(dst), "l"(src), "r"(sz));
}
__device__ __forceinline__ void cp_commit() {
    asm volatile("cp.async.commit_group;");
}
template<int N>
__device__ __forceinline__ void cp_wait() {
    asm volatile("cp.async.wait_group %0;" :: "n"(N));
}

// permuted pair column for split-bf16 GEMM fragments
__device__ __forceinline__ int pair_perm(int p) {
    int q = p & 15;
    return (p & ~15) + (q & 8) + (q & 3) * 2 + ((q >> 2) & 1);
}

__device__ __forceinline__ void split_pack(float x0, float x1, uint32_t& hp, uint32_t& lp) {
    __nv_bfloat16 h0 = __float2bfloat16_rn(x0);
    __nv_bfloat16 h1 = __float2bfloat16_rn(x1);
    float l0f = x0 - __bfloat162float(h0);
    float l1f = x1 - __bfloat162float(h1);
    __nv_bfloat16 l0 = __float2bfloat16_rn(l0f);
    __nv_bfloat16 l1 = __float2bfloat16_rn(l1f);
    hp = (uint32_t)__bfloat16_as_ushort(h0) | ((uint32_t)__bfloat16_as_ushort(h1) << 16);
    lp = (uint32_t)__bfloat16_as_ushort(l0) | ((uint32_t)__bfloat16_as_ushort(l1) << 16);
}

// ---------------------------------------------------------------------------
// Kernel 0: f32 -> split-bf16 pre-conversion (permuted layout)
// ---------------------------------------------------------------------------
__global__ void __launch_bounds__(256)
convert_split(const float* __restrict__ src, int which, int npairs)
{
    int i = blockIdx.x * 256 + threadIdx.x;
    if (i >= npairs) return;
    int row = i >> 10;
    int p = i & 1023;
    float2 v = *(const float2*)(src + (size_t)row * K_ + p * 2);
    uint32_t hp, lp;
    split_pack(v.x, v.y, hp, lp);
    int c = pair_perm(p);
    uint32_t* hi = (which == 0) ? g_xh : (which == 1) ? g_wh : g_pwh;
    uint32_t* lo = (which == 0) ? g_xl : (which == 1) ? g_wl : g_pwl;
    hi[(size_t)row * KP_ + c] = hp;
    lo[(size_t)row * KP_ + c] = lp;
}

// ---------------------------------------------------------------------------
// GEMM core: split-bf16, cp.async 3-stage, BK=32, XOR swizzle, TERM-MAJOR
// inner loop (3 passes over (j,mi) per ks -> same-acc mmas >=16 issues apart).
// Block 128x128, 8 warps = 4m x 2n, warp tile 32x64. 2 CTAs/SM.
// ---------------------------------------------------------------------------
#define GW 16
#define GARR (128 * GW)          // 2048 u32
#define GSTAGE (4 * GARR)        // 8192 u32 = 32 KB

__device__ __forceinline__ void gemm_prefetch(
    uint32_t* sbase, const uint32_t* agh, const uint32_t* agl,
    const uint32_t* bgh, const uint32_t* bgl, int ku, bool aok, int r, int fq)
{
    int sw = (r & 3) << 2;
    int w0 = ((fq ^ sw)) * 4;
    int w1 = (((fq + 4) ^ sw)) * 4;
    uint32_t dA = smaddr(sbase + r * GW);
    cp16(dA + w0, agh + ku,     aok);
    cp16(dA + w1, agh + ku + 4, aok);
    uint32_t dAl = dA + GARR * 4;
    cp16(dAl + w0, agl + ku,     aok);
    cp16(dAl + w1, agl + ku + 4, aok);
    uint32_t dB = dAl + GARR * 4;
    cp16(dB + w0, bgh + ku,     true);
    cp16(dB + w1, bgh + ku + 4, true);
    uint32_t dBl = dB + GARR * 4;
    cp16(dBl + w0, bgl + ku,     true);
    cp16(dBl + w1, bgl + ku + 4, true);
}

__device__ __forceinline__ void gemm_core_bf16s(
    const uint32_t* __restrict__ Ahg, const uint32_t* __restrict__ Alg,
    const uint32_t* __restrict__ Bhg, const uint32_t* __restrict__ Blg,
    int m0, int n0, uint32_t* sm, float acc[2][8][4], int tid)
{
    const int lane = tid & 31, wid = tid >> 5;
    const int g = lane >> 2, t = lane & 3;
    const int mw = (wid >> 1) * 32, nw = (wid & 1) * 64;

    const int r = tid >> 1;
    const int fq = (tid & 1) * 8;
    const bool aok = (m0 + r) < M_;
    const int arow = aok ? (m0 + r) : 0;
    const uint32_t* agh = Ahg + (size_t)arow * KP_ + fq;
    const uint32_t* agl = Alg + (size_t)arow * KP_ + fq;
    const uint32_t* bgh = Bhg + (size_t)(n0 + r) * KP_ + fq;
    const uint32_t* bgl = Blg + (size_t)(n0 + r) * KP_ + fq;

    gemm_prefetch(sm,              agh, agl, bgh, bgl, 0,  aok, r, fq);
    cp_commit();
    gemm_prefetch(sm + GSTAGE,     agh, agl, bgh, bgl, 16, aok, r, fq);
    cp_commit();

    const int swf = (g & 3) << 2;
    const int NIT = KP_ / 16;    // 64

    for (int it = 0; it < NIT; it++) {
        if (it + 1 >= NIT) cp_wait<0>(); else cp_wait<1>();
        __syncthreads();
        if (it + 2 < NIT) {
            gemm_prefetch(sm + ((it + 2) % 3) * GSTAGE, agh, agl, bgh, bgl,
                          (it + 2) * 16, aok, r, fq);
            cp_commit();
        }

        uint32_t* Ah = sm + (it % 3) * GSTAGE;
        uint32_t* Al = Ah + GARR;
        uint32_t* Bh = Al + GARR;
        uint32_t* Bl = Bh + GARR;

#pragma unroll
        for (int ks = 0; ks < 2; ks++) {
            const int wb = (ks * 8 + 2 * t) ^ swf;
            uint32_t ah[2][4], al[2][4];
#pragma unroll
            for (int mi = 0; mi < 2; mi++) {
                int r0 = mw + 16 * mi + g;
                uint2 v0 = *(uint2*)&Ah[r0 * GW + wb];
                uint2 v1 = *(uint2*)&Ah[(r0 + 8) * GW + wb];
                ah[mi][0] = v0.x; ah[mi][2] = v0.y;
                ah[mi][1] = v1.x; ah[mi][3] = v1.y;
                uint2 w0 = *(uint2*)&Al[r0 * GW + wb];
                uint2 w1 = *(uint2*)&Al[(r0 + 8) * GW + wb];
                al[mi][0] = w0.x; al[mi][2] = w0.y;
                al[mi][1] = w1.x; al[mi][3] = w1.y;
            }
            // pass 1: ah x bh  (per-acc term order stays hh -> hl -> lh)
#pragma unroll
            for (int j = 0; j < 8; j++) {
                int cn = nw + 8 * j + g;
                uint2 bh = *(uint2*)&Bh[cn * GW + wb];
#pragma unroll
                for (int mi = 0; mi < 2; mi++)
                    mma16(acc[mi][j], ah[mi][0], ah[mi][1], ah[mi][2], ah[mi][3], bh.x, bh.y);
            }
            // pass 2: ah x bl
#pragma unroll
            for (int j = 0; j < 8; j++) {
                int cn = nw + 8 * j + g;
                uint2 bl = *(uint2*)&Bl[cn * GW + wb];
#pragma unroll
                for (int mi = 0; mi < 2; mi++)
                    mma16(acc[mi][j], ah[mi][0], ah[mi][1], ah[mi][2], ah[mi][3], bl.x, bl.y);
            }
            // pass 3: al x bh (bh reloaded; crossbar has headroom)
#pragma unroll
            for (int j = 0; j < 8; j++) {
                int cn = nw + 8 * j + g;
                uint2 bh = *(uint2*)&Bh[cn * GW + wb];
#pragma unroll
                for (int mi = 0; mi < 2; mi++)
                    mma16(acc[mi][j], al[mi][0], al[mi][1], al[mi][2], al[mi][3], bh.x, bh.y);
            }
        }
    }
}

// ---------------------------------------------------------------------------
// Kernel 1: QKV GEMM + scatter epilogue (R6 version).
// ---------------------------------------------------------------------------
__global__ void __launch_bounds__(256, 2)
qkv_gemm(const float* __restrict__ qb, const float* __restrict__ vb)
{
    extern __shared__ uint32_t smu[];
    float acc[2][8][4];
#pragma unroll
    for (int a = 0; a < 2; a++)
#pragma unroll
        for (int b = 0; b < 8; b++)
#pragma unroll
            for (int c = 0; c < 4; c++) acc[a][b][c] = 0.f;

    const int n0 = blockIdx.x * 128;
    const int m0 = blockIdx.y * 128;
    gemm_core_bf16s(g_xh, g_xl, g_wh, g_wl, m0, n0, smu, acc, threadIdx.x);

    const int lane = threadIdx.x & 31, wid = threadIdx.x >> 5;
    const int g = lane >> 2, t = lane & 3;
    const int mw = (wid >> 1) * 32, nw = (wid & 1) * 64;

    const int tq = n0 >> 11;
    const int h = (n0 & 2047) >> 7;
    float* dst = (tq == 0) ? g_q : ((tq == 1) ? g_k : g_v);

    float2 bias[8];
#pragma unroll
    for (int j = 0; j < 8; j++) {
        int d = nw + 8 * j + 2 * t;
        float b0 = 0.f, b1 = 0.f;
        if (tq == 0) { b0 = qb[h * HD_ + d]; b1 = qb[h * HD_ + d + 1]; }
        else if (tq == 2) { b0 = vb[h * HD_ + d]; b1 = vb[h * HD_ + d + 1]; }
        bias[j] = make_float2(b0, b1);
    }

    const int sl0 = 4 * (t & 1) + (t >> 1);   // perm8(2t); perm8(2t+1) = sl0+2

#pragma unroll
    for (int mi = 0; mi < 2; mi++)
#pragma unroll
        for (int rr = 0; rr < 2; rr++) {
            int gm = m0 + mw + 16 * mi + g + 8 * rr;
            if (gm >= M_) continue;
            int b = gm / L_;
            int l = gm - b * L_;
            float* p = dst + ((size_t)(b * H_ + h) * L_ + l) * HD_;
#pragma unroll
            for (int j = 0; j < 8; j++) {
                float ox = acc[mi][j][2 * rr] + bias[j].x;
                float oy = acc[mi][j][2 * rr + 1] + bias[j].y;
                if (tq == 2) {
                    float2 o = make_float2(tf32r(ox), tf32r(oy));
                    *(float2*)(p + nw + 8 * j + 2 * t) = o;
                } else {
                    int dg = nw + 8 * j;
                    p[dg + sl0]     = ox;
                    p[dg + sl0 + 2] = oy;
                }
            }
        }
}

// ---------------------------------------------------------------------------
// Kernel 2: norm + rope on PERMUTED q/k storage; outputs tf32-rounded.
// ---------------------------------------------------------------------------
__global__ void __launch_bounds__(256)
norm_rope(const float* __restrict__ sml, const float* __restrict__ rope)
{
    const int gw = blockIdx.x * 8 + (threadIdx.x >> 5);
    const int lane = threadIdx.x & 31;
    if (gw >= B_ * H_ * L_) return;
    const int l = gw % L_;
    const int h = (gw / L_) % H_;

    float2 cc = *(const float2*)(rope + (size_t)l * 64 + lane * 2);
    float2 ss = *(const float2*)(rope + (size_t)L_ * 64 + (size_t)l * 64 + lane * 2);
    const float scale = __expf(fminf(sml[h], 4.605170185988091f));
    const size_t base = (size_t)gw * HD_ + (lane >> 1) * 8 + (lane & 1);

    {
        float v0 = g_q[base], v1 = g_q[base + 2], v2 = g_q[base + 4], v3 = g_q[base + 6];
        float ssq = v0 * v0 + v1 * v1 + v2 * v2 + v3 * v3;
#pragma unroll
        for (int o = 16; o; o >>= 1) ssq += __shfl_xor_sync(0xffffffffu, ssq, o);
        float inv = scale / fmaxf(sqrtf(ssq), 1e-12f);
        v0 *= inv; v1 *= inv; v2 *= inv; v3 *= inv;
        g_q[base]     = tf32r(cc.x * v0 - ss.x * v1);
        g_q[base + 2] = tf32r(ss.x * v0 + cc.x * v1);
        g_q[base + 4] = tf32r(cc.y * v2 - ss.y * v3);
        g_q[base + 6] = tf32r(ss.y * v2 + cc.y * v3);
    }
    {
        float v0 = g_k[base], v1 = g_k[base + 2], v2 = g_k[base + 4], v3 = g_k[base + 6];
        float ssq = v0 * v0 + v1 * v1 + v2 * v2 + v3 * v3;
#pragma unroll
        for (int o = 16; o; o >>= 1) ssq += __shfl_xor_sync(0xffffffffu, ssq, o);
        float inv = 1.f / fmaxf(sqrtf(ssq), 1e-12f);
        v0 *= inv; v1 *= inv; v2 *= inv; v3 *= inv;
        g_k[base]     = tf32r(cc.x * v0 - ss.x * v1);
        g_k[base + 2] = tf32r(ss.x * v0 + cc.x * v1);
        g_k[base + 4] = tf32r(cc.y * v2 - ss.y * v3);
        g_k[base + 6] = tf32r(ss.y * v2 + cc.y * v3);
    }
}

// ---------------------------------------------------------------------------
// Kernel 3: flash attention (exact R6 version — best measured).
// ---------------------------------------------------------------------------
#define FW 128
#define FKB (64 * FW)
#define FSTG (2 * FKB)

__device__ __forceinline__ int kend_of(int lq) {
    if (lq >= L_) return 0;
    int ke = 2521;
#pragma unroll
    for (int i = 9; i >= 0; i--)
        if (lq < d_cum[i]) ke = d_cum[i];
    return ke;
}

__device__ __forceinline__ void flash_prefetch(
    float* sm, int s, int k0, const float* kp, const float* vp, int tid)
{
    float* Kb = sm + s * FSTG;
    float* Vb = Kb + FKB;
    int kr = tid >> 2;
    int cb = (tid & 3) * 32;
    bool ok = (k0 + kr) < L_;
    const float* ks = kp + (size_t)(ok ? (k0 + kr) : 0) * HD_ + cb;
    int swk = (kr & 3) << 3;
    uint32_t dK = smaddr(Kb + kr * FW);
#pragma unroll
    for (int i = 0; i < 8; i++)
        cp16(dK + 4 * ((cb + 4 * i) ^ swk), ks + 4 * i, ok);
    int w = kr & 7;
    int slot = (kr & ~7) + (w >> 1) + ((w & 1) << 2);
    int swv = (slot & 3) << 3;
    const float* vs = vp + (size_t)(ok ? (k0 + kr) : 0) * HD_ + cb;
    uint32_t dV = smaddr(Vb + slot * FW);
#pragma unroll
    for (int i = 0; i < 8; i++)
        cp16(dV + 4 * ((cb + 4 * i) ^ swv), vs + 4 * i, ok);
}

__global__ void __launch_bounds__(256, 1)
flash_attn()
{
    extern __shared__ float sm[];

    const int bh = blockIdx.y;
    const int q0 = (gridDim.x - 1 - blockIdx.x) * 128;
    const float* qp = g_q + (size_t)bh * L_ * HD_;
    const float* kp = g_k + (size_t)bh * L_ * HD_;
    const float* vp = g_v + (size_t)bh * L_ * HD_;
    const int tid = threadIdx.x, lane = tid & 31, wid = tid >> 5;
    const int g = lane >> 2, t = lane & 3;
    const int rowbase = wid * 16 + g;
    const int swg = (g & 3) << 3;

    int kmax;
    {
        int lql = min(q0 + 127, L_ - 1);
        kmax = 2521;
#pragma unroll
        for (int i = 9; i >= 0; i--)
            if (lql < d_cum[i]) kmax = d_cum[i];
    }
    const int niter = (kmax + 63) / 64;

    {
        int r = tid >> 1;
        int cb = (tid & 1) * 64;
        bool ok = (q0 + r) < L_;
        const float* src = qp + (size_t)(ok ? (q0 + r) : 0) * HD_ + cb;
        int sw = (r & 3) << 3;
        uint32_t d = smaddr(sm + r * FW);
#pragma unroll
        for (int i = 0; i < 16; i++)
            cp16(d + 4 * ((cb + 4 * i) ^ sw), src + 4 * i, ok);
    }
    cp_commit();
    flash_prefetch(sm, 1, 0, kp, vp, tid);
    cp_commit();
    if (niter > 1) flash_prefetch(sm, 2, 64, kp, vp, tid);
    cp_commit();

    cp_wait<2>();
    __syncthreads();

    uint32_t qf[16][4];
#pragma unroll
    for (int kk8 = 0; kk8 < 16; kk8++) {
        int wb = (kk8 * 8 + 2 * t) ^ swg;
        uint2 a0 = *(const uint2*)&sm[rowbase * FW + wb];
        uint2 a1 = *(const uint2*)&sm[(rowbase + 8) * FW + wb];
        qf[kk8][0] = a0.x; qf[kk8][2] = a0.y;
        qf[kk8][1] = a1.x; qf[kk8][3] = a1.y;
    }
    __syncthreads();

    const int kend0 = kend_of(q0 + rowbase);
    const int kend1 = kend_of(q0 + rowbase + 8);

    float m0v = -1e30f, m1v = -1e30f, l0v = 0.f, l1v = 0.f;
    float O[16][4];
#pragma unroll
    for (int j = 0; j < 16; j++)
#pragma unroll
        for (int c = 0; c < 4; c++) O[j][c] = 0.f;

    for (int it = 0; it < niter; it++) {
        const int k0 = it * 64;
        if (it + 1 >= niter) cp_wait<0>(); else cp_wait<1>();
        __syncthreads();
        if (it + 2 < niter) {
            flash_prefetch(sm, it % 3, (it + 2) * 64, kp, vp, tid);
            cp_commit();
        }

        float* Kb = sm + ((it + 1) % 3) * FSTG;
        float* Vb = Kb + FKB;

        float sc[8][4];
#pragma unroll
        for (int j = 0; j < 8; j++)
#pragma unroll
            for (int c = 0; c < 4; c++) sc[j][c] = 0.f;

#pragma unroll
        for (int kk8 = 0; kk8 < 16; kk8++) {
            int wb = (kk8 * 8 + 2 * t) ^ swg;
#pragma unroll
            for (int j = 0; j < 8; j++) {
                uint2 bb = *(const uint2*)&Kb[(8 * j + g) * FW + wb];
                mma8(sc[j], qf[kk8][0], qf[kk8][1], qf[kk8][2], qf[kk8][3], bb.x, bb.y);
            }
        }

        float rmax0 = -1e30f, rmax1 = -1e30f;
#pragma unroll
        for (int j = 0; j < 8; j++) {
            int c0 = k0 + 8 * j + 2 * t, c1 = c0 + 1;
            if (c0 >= kend0) sc[j][0] = -1e30f;
            if (c1 >= kend0) sc[j][1] = -1e30f;
            if (c0 >= kend1) sc[j][2] = -1e30f;
            if (c1 >= kend1) sc[j][3] = -1e30f;
            rmax0 = fmaxf(rmax0, fmaxf(sc[j][0], sc[j][1]));
            rmax1 = fmaxf(rmax1, fmaxf(sc[j][2], sc[j][3]));
        }
        rmax0 = fmaxf(rmax0, __shfl_xor_sync(0xffffffffu, rmax0, 1));
        rmax0 = fmaxf(rmax0, __shfl_xor_sync(0xffffffffu, rmax0, 2));
        rmax1 = fmaxf(rmax1, __shfl_xor_sync(0xffffffffu, rmax1, 1));
        rmax1 = fmaxf(rmax1, __shfl_xor_sync(0xffffffffu, rmax1, 2));

        float mn0 = fmaxf(m0v, rmax0), mn1 = fmaxf(m1v, rmax1);
        float al0 = __expf(m0v - mn0), al1 = __expf(m1v - mn1);
        float rs0 = 0.f, rs1 = 0.f;
#pragma unroll
        for (int j = 0; j < 8; j++) {
            float p0 = (sc[j][0] > -5e29f) ? __expf(sc[j][0] - mn0) : 0.f;
            float p1 = (sc[j][1] > -5e29f) ? __expf(sc[j][1] - mn0) : 0.f;
            float p2 = (sc[j][2] > -5e29f) ? __expf(sc[j][2] - mn1) : 0.f;
            float p3 = (sc[j][3] > -5e29f) ? __expf(sc[j][3] - mn1) : 0.f;
            rs0 += p0 + p1;
            rs1 += p2 + p3;
            sc[j][0] = p0; sc[j][1] = p1; sc[j][2] = p2; sc[j][3] = p3;
        }
        rs0 += __shfl_xor_sync(0xffffffffu, rs0, 1);
        rs0 += __shfl_xor_sync(0xffffffffu, rs0, 2);
        rs1 += __shfl_xor_sync(0xffffffffu, rs1, 1);
        rs1 += __shfl_xor_sync(0xffffffffu, rs1, 2);
        l0v = l0v * al0 + rs0;
        l1v = l1v * al1 + rs1;
        m0v = mn0; m1v = mn1;

#pragma unroll
        for (int j = 0; j < 16; j++) {
            O[j][0] *= al0; O[j][1] *= al0;
            O[j][2] *= al1; O[j][3] *= al1;
        }

        const int swv = t << 3;
#pragma unroll
        for (int c = 0; c < 8; c++) {
            uint32_t a0 = f2tf(sc[c][0]);
            uint32_t a1 = f2tf(sc[c][2]);
            uint32_t a2 = f2tf(sc[c][1]);
            uint32_t a3 = f2tf(sc[c][3]);
            const float* v0 = Vb + (8 * c + t) * FW;
            const float* v1 = Vb + (8 * c + t + 4) * FW;
#pragma unroll
            for (int j = 0; j < 16; j++) {
                int wv = (g + 8 * j) ^ swv;
                uint32_t b0 = __float_as_uint(v0[wv]);
                uint32_t b1 = __float_as_uint(v1[wv]);
                mma8(O[j], a0, a1, a2, a3, b0, b1);
            }
        }
    }

    // epilogue: normalize, convert to split-bf16 pairs, write permuted layout
    const int b = bh >> 4;
    const int h = bh & 15;
#pragma unroll
    for (int rr = 0; rr < 2; rr++) {
        int lq = q0 + rowbase + 8 * rr;
        if (lq >= L_) continue;
        float inv = 1.f / (rr ? l1v : l0v);
        size_t rowoff = (size_t)(b * L_ + lq) * KP_;
#pragma unroll
        for (int j = 0; j < 16; j++) {
            float x0 = O[j][2 * rr] * inv;
            float x1 = O[j][2 * rr + 1] * inv;
            uint32_t hp, lp;
            split_pack(x0, x1, hp, lp);
            int p = h * 64 + 4 * j + t;
            int c = pair_perm(p);
            g_aoh[rowoff + c] = hp;
            g_aol[rowoff + c] = lp;
        }
    }
}

// ---------------------------------------------------------------------------
// Kernel 4: projection GEMM (R6 version)
// ---------------------------------------------------------------------------
__global__ void __launch_bounds__(256, 2)
proj_gemm(const float* __restrict__ pb, float* __restrict__ out)
{
    extern __shared__ uint32_t smu[];
    float acc[2][8][4];
#pragma unroll
    for (int a = 0; a < 2; a++)
#pragma unroll
        for (int b = 0; b < 8; b++)
#pragma unroll
            for (int c = 0; c < 4; c++) acc[a][b][c] = 0.f;

    const int n0 = blockIdx.x * 128;
    const int m0 = blockIdx.y * 128;
    gemm_core_bf16s(g_aoh, g_aol, g_pwh, g_pwl, m0, n0, smu, acc, threadIdx.x);

    const int lane = threadIdx.x & 31, wid = threadIdx.x >> 5;
    const int g = lane >> 2, t = lane & 3;
    const int mw = (wid >> 1) * 32, nw = (wid & 1) * 64;

    float2 bias[8];
#pragma unroll
    for (int j = 0; j < 8; j++) {
        int n = n0 + nw + 8 * j + 2 * t;
        bias[j] = make_float2(pb[n], pb[n + 1]);
    }

#pragma unroll
    for (int mi = 0; mi < 2; mi++)
#pragma unroll
        for (int rr = 0; rr < 2; rr++) {
            int gm = m0 + mw + 16 * mi + g + 8 * rr;
            if (gm >= M_) continue;
            float* p = out + (size_t)gm * C_ + n0 + nw;
#pragma unroll
            for (int j = 0; j < 8; j++) {
                float2 o;
                o.x = acc[mi][j][2 * rr] + bias[j].x;
                o.y = acc[mi][j][2 * rr + 1] + bias[j].y;
                *(float2*)(p + 8 * j + 2 * t) = o;
            }
        }
}

// ---------------------------------------------------------------------------
// launch
// ---------------------------------------------------------------------------
extern "C" void kernel_launch(void* const* d_in, const int* in_sizes, int n_in,
                              void* d_out, int out_size)
{
    const float* x    = (const float*)d_in[0];
    const float* Wqkv = (const float*)d_in[1];
    const float* qb   = (const float*)d_in[2];
    const float* vb   = (const float*)d_in[3];
    const float* sml  = (const float*)d_in[4];
    const float* pW   = (const float*)d_in[5];
    const float* pb   = (const float*)d_in[6];
    const float* rope = (const float*)d_in[7];
    float* out = (float*)d_out;

    const size_t gemm_shm  = (size_t)3 * GSTAGE * sizeof(uint32_t);   // 98,304 B
    const size_t flash_shm = (size_t)3 * FSTG * sizeof(float);        // 196,608 B

    cudaFuncSetAttribute(qkv_gemm, cudaFuncAttributeMaxDynamicSharedMemorySize, (int)gemm_shm);
    cudaFuncSetAttribute(proj_gemm, cudaFuncAttributeMaxDynamicSharedMemorySize, (int)gemm_shm);
    cudaFuncSetAttribute(flash_attn, cudaFuncAttributeMaxDynamicSharedMemorySize, (int)flash_shm);

    {
        int np;
        np = M_ * KP_;    convert_split<<<(np + 255) / 256, 256>>>(x, 0, np);
        np = NQKV * KP_;  convert_split<<<(np + 255) / 256, 256>>>(Wqkv, 1, np);
        np = C_ * KP_;    convert_split<<<(np + 255) / 256, 256>>>(pW, 2, np);
    }

    dim3 g1(NQKV / 128, (M_ + 127) / 128);   // 48 x 40
    qkv_gemm<<<g1, 256, gemm_shm>>>(qb, vb);

    int nwarps = B_ * H_ * L_;
    norm_rope<<<(nwarps + 7) / 8, 256>>>(sml, rope);

    dim3 g3((L_ + 127) / 128, B_ * H_);      // 20 x 32
    flash_attn<<<g3, 256, flash_shm>>>();

    dim3 g4(C_ / 128, (M_ + 127) / 128);     // 16 x 40
    proj_gemm<<<g4, 256, gemm_shm>>>(pb, out);
}

// round 13
// speedup vs baseline: 2.2693x; 1.4001x over previous
#include <cuda_runtime.h>
#include <cuda_bf16.h>
#include <cuda_fp16.h>
#include <cstdint>
#include <math.h>

// ---------------------------------------------------------------------------
// Problem constants
// ---------------------------------------------------------------------------
#define B_   2
#define L_   2521
#define C_   2048
#define H_   16
#define HD_  128
#define M_   (B_ * L_)          // 5042
#define K_   2048
#define KP_  1024               // K/2 u32 pairs per row
#define NQKV 6144

__device__ __constant__ int d_cum[10] = {1, 5, 21, 57, 121, 265, 521, 921, 1497, 2521};

// f32 scratch; q/k stored d-PERMUTED (perm8 within 8-groups) and tf32-rounded,
// v stored plain d-order, tf32-rounded.
__device__ float g_q[B_ * H_ * L_ * HD_];
__device__ float g_k[B_ * H_ * L_ * HD_];
__device__ float g_v[B_ * H_ * L_ * HD_];

// fp16 single-term operands for qkv GEMM (u32 = packed half2, pair-permuted)
__device__ uint32_t g_xf[M_ * KP_];
__device__ uint32_t g_wf[NQKV * KP_];
// split-bf16 operands for proj GEMM (pair-permuted)
__device__ uint32_t g_pwh[C_ * KP_],  g_pwl[C_ * KP_];
__device__ uint32_t g_aoh[M_ * KP_],  g_aol[M_ * KP_];

// ---------------------------------------------------------------------------
// helpers
// ---------------------------------------------------------------------------
__device__ __forceinline__ uint32_t f2tf(float x) {
    uint32_t r;
    asm("cvt.rna.tf32.f32 %0, %1;" : "=r"(r) : "f"(x));
    return r;
}
__device__ __forceinline__ float tf32r(float x) { return __uint_as_float(f2tf(x)); }

__device__ __forceinline__ void mma8(float* c,
                                     uint32_t a0, uint32_t a1, uint32_t a2, uint32_t a3,
                                     uint32_t b0, uint32_t b1)
{
    asm volatile(
        "mma.sync.aligned.m16n8k8.row.col.f32.tf32.tf32.f32 "
        "{%0,%1,%2,%3}, {%4,%5,%6,%7}, {%8,%9}, {%0,%1,%2,%3};"
        : "+f"(c[0]), "+f"(c[1]), "+f"(c[2]), "+f"(c[3])
        : "r"(a0), "r"(a1), "r"(a2), "r"(a3), "r"(b0), "r"(b1));
}

__device__ __forceinline__ void mma16bf(float* c,
                                        uint32_t a0, uint32_t a1, uint32_t a2, uint32_t a3,
                                        uint32_t b0, uint32_t b1)
{
    asm volatile(
        "mma.sync.aligned.m16n8k16.row.col.f32.bf16.bf16.f32 "
        "{%0,%1,%2,%3}, {%4,%5,%6,%7}, {%8,%9}, {%0,%1,%2,%3};"
        : "+f"(c[0]), "+f"(c[1]), "+f"(c[2]), "+f"(c[3])
        : "r"(a0), "r"(a1), "r"(a2), "r"(a3), "r"(b0), "r"(b1));
}

__device__ __forceinline__ void mma16f(float* c,
                                       uint32_t a0, uint32_t a1, uint32_t a2, uint32_t a3,
                                       uint32_t b0, uint32_t b1)
{
    asm volatile(
        "mma.sync.aligned.m16n8k16.row.col.f32.f16.f16.f32 "
        "{%0,%1,%2,%3}, {%4,%5,%6,%7}, {%8,%9}, {%0,%1,%2,%3};"
        : "+f"(c[0]), "+f"(c[1]), "+f"(c[2]), "+f"(c[3])
        : "r"(a0), "r"(a1), "r"(a2), "r"(a3), "r"(b0), "r"(b1));
}

__device__ __forceinline__ uint32_t smaddr(const void* p) {
    return (uint32_t)__cvta_generic_to_shared(p);
}
__device__ __forceinline__ void cp16(uint32_t dst, const void* src, bool pred) {
    int sz = pred ? 16 : 0;
    asm volatile("cp.async.cg.shared.global [%0], [%1], 16, %2;"
                 :: "r"(dst), "l"(src), "r"(sz));
}
__device__ __forceinline__ void cp_commit() {
    asm volatile("cp.async.commit_group;");
}
template<int N>
__device__ __forceinline__ void cp_wait() {
    asm volatile("cp.async.wait_group %0;" :: "n"(N));
}

// permuted pair column for mma fragment-order loads
__device__ __forceinline__ int pair_perm(int p) {
    int q = p & 15;
    return (p & ~15) + (q & 8) + (q & 3) * 2 + ((q >> 2) & 1);
}

__device__ __forceinline__ void split_pack(float x0, float x1, uint32_t& hp, uint32_t& lp) {
    __nv_bfloat16 h0 = __float2bfloat16_rn(x0);
    __nv_bfloat16 h1 = __float2bfloat16_rn(x1);
    float l0f = x0 - __bfloat162float(h0);
    float l1f = x1 - __bfloat162float(h1);
    __nv_bfloat16 l0 = __float2bfloat16_rn(l0f);
    __nv_bfloat16 l1 = __float2bfloat16_rn(l1f);
    hp = (uint32_t)__bfloat16_as_ushort(h0) | ((uint32_t)__bfloat16_as_ushort(h1) << 16);
    lp = (uint32_t)__bfloat16_as_ushort(l0) | ((uint32_t)__bfloat16_as_ushort(l1) << 16);
}

// ---------------------------------------------------------------------------
// Kernel 0a: f32 -> fp16 pack; destination selected IN DEVICE CODE (which:
// 0 = g_xf, 1 = g_wf). Passing __device__ globals from host is invalid.
// ---------------------------------------------------------------------------
__global__ void __launch_bounds__(256)
convert_f16(const float* __restrict__ src, int which, int npairs)
{
    int i = blockIdx.x * 256 + threadIdx.x;
    if (i >= npairs) return;
    int row = i >> 10;
    int p = i & 1023;
    float2 v = *(const float2*)(src + (size_t)row * K_ + p * 2);
    __half h0 = __float2half_rn(v.x);
    __half h1 = __float2half_rn(v.y);
    uint32_t hp = (uint32_t)__half_as_ushort(h0) | ((uint32_t)__half_as_ushort(h1) << 16);
    uint32_t* dst = (which == 0) ? g_xf : g_wf;
    dst[(size_t)row * KP_ + pair_perm(p)] = hp;
}

__global__ void __launch_bounds__(256)
convert_split_pw(const float* __restrict__ src, int npairs)
{
    int i = blockIdx.x * 256 + threadIdx.x;
    if (i >= npairs) return;
    int row = i >> 10;
    int p = i & 1023;
    float2 v = *(const float2*)(src + (size_t)row * K_ + p * 2);
    uint32_t hp, lp;
    split_pack(v.x, v.y, hp, lp);
    int c = pair_perm(p);
    g_pwh[(size_t)row * KP_ + c] = hp;
    g_pwl[(size_t)row * KP_ + c] = lp;
}

// ---------------------------------------------------------------------------
// Single-term fp16 GEMM core (qkv): C[128x128]=A*B^T, BK=32, 3-stage cp.async,
// XOR swizzle, 8 warps = 4m x 2n, warp tile 32x64.
// ---------------------------------------------------------------------------
#define GW 16
#define QARR (128 * GW)          // 2048 u32
#define QSTG (2 * QARR)          // A + B = 4096 u32 = 16 KB

__device__ __forceinline__ void qkv_prefetch(
    uint32_t* sbase, const uint32_t* ag, const uint32_t* bg,
    int ku, bool aok, int r, int fq)
{
    int sw = (r & 3) << 2;
    int w0 = (fq ^ sw) * 4;
    int w1 = ((fq + 4) ^ sw) * 4;
    uint32_t dA = smaddr(sbase + r * GW);
    cp16(dA + w0, ag + ku,     aok);
    cp16(dA + w1, ag + ku + 4, aok);
    uint32_t dB = dA + QARR * 4;
    cp16(dB + w0, bg + ku,     true);
    cp16(dB + w1, bg + ku + 4, true);
}

__global__ void __launch_bounds__(256, 2)
qkv_gemm(const float* __restrict__ qb, const float* __restrict__ vb)
{
    extern __shared__ uint32_t smu[];
    float acc[2][8][4];
#pragma unroll
    for (int a = 0; a < 2; a++)
#pragma unroll
        for (int b = 0; b < 8; b++)
#pragma unroll
            for (int c = 0; c < 4; c++) acc[a][b][c] = 0.f;

    const int tid = threadIdx.x;
    const int lane = tid & 31, wid = tid >> 5;
    const int g = lane >> 2, t = lane & 3;
    const int mw = (wid >> 1) * 32, nw = (wid & 1) * 64;
    const int n0 = blockIdx.x * 128;
    const int m0 = blockIdx.y * 128;

    const int r = tid >> 1;
    const int fq = (tid & 1) * 8;
    const bool aok = (m0 + r) < M_;
    const uint32_t* ag = g_xf + (size_t)(aok ? m0 + r : 0) * KP_ + fq;
    const uint32_t* bg = g_wf + (size_t)(n0 + r) * KP_ + fq;

    qkv_prefetch(smu,            ag, bg, 0,  aok, r, fq);
    cp_commit();
    qkv_prefetch(smu + QSTG,     ag, bg, 16, aok, r, fq);
    cp_commit();

    const int swf = (g & 3) << 2;
    const int NIT = KP_ / 16;    // 64

    for (int it = 0; it < NIT; it++) {
        if (it + 1 >= NIT) cp_wait<0>(); else cp_wait<1>();
        __syncthreads();
        if (it + 2 < NIT) {
            qkv_prefetch(smu + ((it + 2) % 3) * QSTG, ag, bg, (it + 2) * 16, aok, r, fq);
            cp_commit();
        }

        uint32_t* As = smu + (it % 3) * QSTG;
        uint32_t* Bs = As + QARR;

#pragma unroll
        for (int ks = 0; ks < 2; ks++) {
            const int wb = (ks * 8 + 2 * t) ^ swf;
            uint32_t ah[2][4];
#pragma unroll
            for (int mi = 0; mi < 2; mi++) {
                int r0 = mw + 16 * mi + g;
                uint2 v0 = *(uint2*)&As[r0 * GW + wb];
                uint2 v1 = *(uint2*)&As[(r0 + 8) * GW + wb];
                ah[mi][0] = v0.x; ah[mi][2] = v0.y;
                ah[mi][1] = v1.x; ah[mi][3] = v1.y;
            }
#pragma unroll
            for (int j = 0; j < 8; j++) {
                int cn = nw + 8 * j + g;
                uint2 bh = *(uint2*)&Bs[cn * GW + wb];
#pragma unroll
                for (int mi = 0; mi < 2; mi++)
                    mma16f(acc[mi][j], ah[mi][0], ah[mi][1], ah[mi][2], ah[mi][3], bh.x, bh.y);
            }
        }
    }

    // epilogue (R6 layout): q/k d-permuted, v tf32-rounded
    const int tq = n0 >> 11;
    const int h = (n0 & 2047) >> 7;
    float* dst = (tq == 0) ? g_q : ((tq == 1) ? g_k : g_v);

    float2 bias[8];
#pragma unroll
    for (int j = 0; j < 8; j++) {
        int d = nw + 8 * j + 2 * t;
        float b0 = 0.f, b1 = 0.f;
        if (tq == 0) { b0 = qb[h * HD_ + d]; b1 = qb[h * HD_ + d + 1]; }
        else if (tq == 2) { b0 = vb[h * HD_ + d]; b1 = vb[h * HD_ + d + 1]; }
        bias[j] = make_float2(b0, b1);
    }

    const int sl0 = 4 * (t & 1) + (t >> 1);   // perm8(2t); perm8(2t+1) = sl0+2

#pragma unroll
    for (int mi = 0; mi < 2; mi++)
#pragma unroll
        for (int rr = 0; rr < 2; rr++) {
            int gm = m0 + mw + 16 * mi + g + 8 * rr;
            if (gm >= M_) continue;
            int b = gm / L_;
            int l = gm - b * L_;
            float* p = dst + ((size_t)(b * H_ + h) * L_ + l) * HD_;
#pragma unroll
            for (int j = 0; j < 8; j++) {
                float ox = acc[mi][j][2 * rr] + bias[j].x;
                float oy = acc[mi][j][2 * rr + 1] + bias[j].y;
                if (tq == 2) {
                    float2 o = make_float2(tf32r(ox), tf32r(oy));
                    *(float2*)(p + nw + 8 * j + 2 * t) = o;
                } else {
                    int dg = nw + 8 * j;
                    p[dg + sl0]     = ox;
                    p[dg + sl0 + 2] = oy;
                }
            }
        }
}

// ---------------------------------------------------------------------------
// split-bf16 GEMM core (proj, R6 config): 3-stage cp.async, XOR swizzle.
// ---------------------------------------------------------------------------
#define GARR (128 * GW)          // 2048 u32
#define GSTAGE (4 * GARR)        // 8192 u32 = 32 KB

__device__ __forceinline__ void gemm_prefetch(
    uint32_t* sbase, const uint32_t* agh, const uint32_t* agl,
    const uint32_t* bgh, const uint32_t* bgl, int ku, bool aok, int r, int fq)
{
    int sw = (r & 3) << 2;
    int w0 = ((fq ^ sw)) * 4;
    int w1 = (((fq + 4) ^ sw)) * 4;
    uint32_t dA = smaddr(sbase + r * GW);
    cp16(dA + w0, agh + ku,     aok);
    cp16(dA + w1, agh + ku + 4, aok);
    uint32_t dAl = dA + GARR * 4;
    cp16(dAl + w0, agl + ku,     aok);
    cp16(dAl + w1, agl + ku + 4, aok);
    uint32_t dB = dAl + GARR * 4;
    cp16(dB + w0, bgh + ku,     true);
    cp16(dB + w1, bgh + ku + 4, true);
    uint32_t dBl = dB + GARR * 4;
    cp16(dBl + w0, bgl + ku,     true);
    cp16(dBl + w1, bgl + ku + 4, true);
}

__global__ void __launch_bounds__(256, 2)
proj_gemm(const float* __restrict__ pb, float* __restrict__ out)
{
    extern __shared__ uint32_t smu[];
    float acc[2][8][4];
#pragma unroll
    for (int a = 0; a < 2; a++)
#pragma unroll
        for (int b = 0; b < 8; b++)
#pragma unroll
            for (int c = 0; c < 4; c++) acc[a][b][c] = 0.f;

    const int tid = threadIdx.x;
    const int lane = tid & 31, wid = tid >> 5;
    const int g = lane >> 2, t = lane & 3;
    const int mw = (wid >> 1) * 32, nw = (wid & 1) * 64;
    const int n0 = blockIdx.x * 128;
    const int m0 = blockIdx.y * 128;

    const int r = tid >> 1;
    const int fq = (tid & 1) * 8;
    const bool aok = (m0 + r) < M_;
    const int arow = aok ? (m0 + r) : 0;
    const uint32_t* agh = g_aoh + (size_t)arow * KP_ + fq;
    const uint32_t* agl = g_aol + (size_t)arow * KP_ + fq;
    const uint32_t* bgh = g_pwh + (size_t)(n0 + r) * KP_ + fq;
    const uint32_t* bgl = g_pwl + (size_t)(n0 + r) * KP_ + fq;

    gemm_prefetch(smu,              agh, agl, bgh, bgl, 0,  aok, r, fq);
    cp_commit();
    gemm_prefetch(smu + GSTAGE,     agh, agl, bgh, bgl, 16, aok, r, fq);
    cp_commit();

    const int swf = (g & 3) << 2;
    const int NIT = KP_ / 16;

    for (int it = 0; it < NIT; it++) {
        if (it + 1 >= NIT) cp_wait<0>(); else cp_wait<1>();
        __syncthreads();
        if (it + 2 < NIT) {
            gemm_prefetch(smu + ((it + 2) % 3) * GSTAGE, agh, agl, bgh, bgl,
                          (it + 2) * 16, aok, r, fq);
            cp_commit();
        }

        uint32_t* Ah = smu + (it % 3) * GSTAGE;
        uint32_t* Al = Ah + GARR;
        uint32_t* Bh = Al + GARR;
        uint32_t* Bl = Bh + GARR;

#pragma unroll
        for (int ks = 0; ks < 2; ks++) {
            const int wb = (ks * 8 + 2 * t) ^ swf;
            uint32_t ah[2][4], al[2][4];
#pragma unroll
            for (int mi = 0; mi < 2; mi++) {
                int r0 = mw + 16 * mi + g;
                uint2 v0 = *(uint2*)&Ah[r0 * GW + wb];
                uint2 v1 = *(uint2*)&Ah[(r0 + 8) * GW + wb];
                ah[mi][0] = v0.x; ah[mi][2] = v0.y;
                ah[mi][1] = v1.x; ah[mi][3] = v1.y;
                uint2 w0 = *(uint2*)&Al[r0 * GW + wb];
                uint2 w1 = *(uint2*)&Al[(r0 + 8) * GW + wb];
                al[mi][0] = w0.x; al[mi][2] = w0.y;
                al[mi][1] = w1.x; al[mi][3] = w1.y;
            }
#pragma unroll
            for (int j = 0; j < 8; j++) {
                int cn = nw + 8 * j + g;
                uint2 bh = *(uint2*)&Bh[cn * GW + wb];
                uint2 bl = *(uint2*)&Bl[cn * GW + wb];
#pragma unroll
                for (int mi = 0; mi < 2; mi++) {
                    mma16bf(acc[mi][j], ah[mi][0], ah[mi][1], ah[mi][2], ah[mi][3], bh.x, bh.y);
                    mma16bf(acc[mi][j], ah[mi][0], ah[mi][1], ah[mi][2], ah[mi][3], bl.x, bl.y);
                    mma16bf(acc[mi][j], al[mi][0], al[mi][1], al[mi][2], al[mi][3], bh.x, bh.y);
                }
            }
        }
    }

    float2 bias[8];
#pragma unroll
    for (int j = 0; j < 8; j++) {
        int n = n0 + nw + 8 * j + 2 * t;
        bias[j] = make_float2(pb[n], pb[n + 1]);
    }

#pragma unroll
    for (int mi = 0; mi < 2; mi++)
#pragma unroll
        for (int rr = 0; rr < 2; rr++) {
            int gm = m0 + mw + 16 * mi + g + 8 * rr;
            if (gm >= M_) continue;
            float* p = out + (size_t)gm * C_ + n0 + nw;
#pragma unroll
            for (int j = 0; j < 8; j++) {
                float2 o;
                o.x = acc[mi][j][2 * rr] + bias[j].x;
                o.y = acc[mi][j][2 * rr + 1] + bias[j].y;
                *(float2*)(p + 8 * j + 2 * t) = o;
            }
        }
}

// ---------------------------------------------------------------------------
// Kernel 2: norm + rope on PERMUTED q/k storage; outputs tf32-rounded.
// ---------------------------------------------------------------------------
__global__ void __launch_bounds__(256)
norm_rope(const float* __restrict__ sml, const float* __restrict__ rope)
{
    const int gw = blockIdx.x * 8 + (threadIdx.x >> 5);
    const int lane = threadIdx.x & 31;
    if (gw >= B_ * H_ * L_) return;
    const int l = gw % L_;
    const int h = (gw / L_) % H_;

    float2 cc = *(const float2*)(rope + (size_t)l * 64 + lane * 2);
    float2 ss = *(const float2*)(rope + (size_t)L_ * 64 + (size_t)l * 64 + lane * 2);
    const float scale = __expf(fminf(sml[h], 4.605170185988091f));
    const size_t base = (size_t)gw * HD_ + (lane >> 1) * 8 + (lane & 1);

    {
        float v0 = g_q[base], v1 = g_q[base + 2], v2 = g_q[base + 4], v3 = g_q[base + 6];
        float ssq = v0 * v0 + v1 * v1 + v2 * v2 + v3 * v3;
#pragma unroll
        for (int o = 16; o; o >>= 1) ssq += __shfl_xor_sync(0xffffffffu, ssq, o);
        float inv = scale / fmaxf(sqrtf(ssq), 1e-12f);
        v0 *= inv; v1 *= inv; v2 *= inv; v3 *= inv;
        g_q[base]     = tf32r(cc.x * v0 - ss.x * v1);
        g_q[base + 2] = tf32r(ss.x * v0 + cc.x * v1);
        g_q[base + 4] = tf32r(cc.y * v2 - ss.y * v3);
        g_q[base + 6] = tf32r(ss.y * v2 + cc.y * v3);
    }
    {
        float v0 = g_k[base], v1 = g_k[base + 2], v2 = g_k[base + 4], v3 = g_k[base + 6];
        float ssq = v0 * v0 + v1 * v1 + v2 * v2 + v3 * v3;
#pragma unroll
        for (int o = 16; o; o >>= 1) ssq += __shfl_xor_sync(0xffffffffu, ssq, o);
        float inv = 1.f / fmaxf(sqrtf(ssq), 1e-12f);
        v0 *= inv; v1 *= inv; v2 *= inv; v3 *= inv;
        g_k[base]     = tf32r(cc.x * v0 - ss.x * v1);
        g_k[base + 2] = tf32r(ss.x * v0 + cc.x * v1);
        g_k[base + 4] = tf32r(cc.y * v2 - ss.y * v3);
        g_k[base + 6] = tf32r(ss.y * v2 + cc.y * v3);
    }
}

// ---------------------------------------------------------------------------
// Kernel 3: flash attention (exact R6 version — best measured).
// ---------------------------------------------------------------------------
#define FW 128
#define FKB (64 * FW)
#define FSTG (2 * FKB)

__device__ __forceinline__ int kend_of(int lq) {
    if (lq >= L_) return 0;
    int ke = 2521;
#pragma unroll
    for (int i = 9; i >= 0; i--)
        if (lq < d_cum[i]) ke = d_cum[i];
    return ke;
}

__device__ __forceinline__ void flash_prefetch(
    float* sm, int s, int k0, const float* kp, const float* vp, int tid)
{
    float* Kb = sm + s * FSTG;
    float* Vb = Kb + FKB;
    int kr = tid >> 2;
    int cb = (tid & 3) * 32;
    bool ok = (k0 + kr) < L_;
    const float* ks = kp + (size_t)(ok ? (k0 + kr) : 0) * HD_ + cb;
    int swk = (kr & 3) << 3;
    uint32_t dK = smaddr(Kb + kr * FW);
#pragma unroll
    for (int i = 0; i < 8; i++)
        cp16(dK + 4 * ((cb + 4 * i) ^ swk), ks + 4 * i, ok);
    int w = kr & 7;
    int slot = (kr & ~7) + (w >> 1) + ((w & 1) << 2);
    int swv = (slot & 3) << 3;
    const float* vs = vp + (size_t)(ok ? (k0 + kr) : 0) * HD_ + cb;
    uint32_t dV = smaddr(Vb + slot * FW);
#pragma unroll
    for (int i = 0; i < 8; i++)
        cp16(dV + 4 * ((cb + 4 * i) ^ swv), vs + 4 * i, ok);
}

__global__ void __launch_bounds__(256, 1)
flash_attn()
{
    extern __shared__ float sm[];

    const int bh = blockIdx.y;
    const int q0 = (gridDim.x - 1 - blockIdx.x) * 128;
    const float* qp = g_q + (size_t)bh * L_ * HD_;
    const float* kp = g_k + (size_t)bh * L_ * HD_;
    const float* vp = g_v + (size_t)bh * L_ * HD_;
    const int tid = threadIdx.x, lane = tid & 31, wid = tid >> 5;
    const int g = lane >> 2, t = lane & 3;
    const int rowbase = wid * 16 + g;
    const int swg = (g & 3) << 3;

    int kmax;
    {
        int lql = min(q0 + 127, L_ - 1);
        kmax = 2521;
#pragma unroll
        for (int i = 9; i >= 0; i--)
            if (lql < d_cum[i]) kmax = d_cum[i];
    }
    const int niter = (kmax + 63) / 64;

    {
        int r = tid >> 1;
        int cb = (tid & 1) * 64;
        bool ok = (q0 + r) < L_;
        const float* src = qp + (size_t)(ok ? (q0 + r) : 0) * HD_ + cb;
        int sw = (r & 3) << 3;
        uint32_t d = smaddr(sm + r * FW);
#pragma unroll
        for (int i = 0; i < 16; i++)
            cp16(d + 4 * ((cb + 4 * i) ^ sw), src + 4 * i, ok);
    }
    cp_commit();
    flash_prefetch(sm, 1, 0, kp, vp, tid);
    cp_commit();
    if (niter > 1) flash_prefetch(sm, 2, 64, kp, vp, tid);
    cp_commit();

    cp_wait<2>();
    __syncthreads();

    uint32_t qf[16][4];
#pragma unroll
    for (int kk8 = 0; kk8 < 16; kk8++) {
        int wb = (kk8 * 8 + 2 * t) ^ swg;
        uint2 a0 = *(const uint2*)&sm[rowbase * FW + wb];
        uint2 a1 = *(const uint2*)&sm[(rowbase + 8) * FW + wb];
        qf[kk8][0] = a0.x; qf[kk8][2] = a0.y;
        qf[kk8][1] = a1.x; qf[kk8][3] = a1.y;
    }
    __syncthreads();

    const int kend0 = kend_of(q0 + rowbase);
    const int kend1 = kend_of(q0 + rowbase + 8);

    float m0v = -1e30f, m1v = -1e30f, l0v = 0.f, l1v = 0.f;
    float O[16][4];
#pragma unroll
    for (int j = 0; j < 16; j++)
#pragma unroll
        for (int c = 0; c < 4; c++) O[j][c] = 0.f;

    for (int it = 0; it < niter; it++) {
        const int k0 = it * 64;
        if (it + 1 >= niter) cp_wait<0>(); else cp_wait<1>();
        __syncthreads();
        if (it + 2 < niter) {
            flash_prefetch(sm, it % 3, (it + 2) * 64, kp, vp, tid);
            cp_commit();
        }

        float* Kb = sm + ((it + 1) % 3) * FSTG;
        float* Vb = Kb + FKB;

        float sc[8][4];
#pragma unroll
        for (int j = 0; j < 8; j++)
#pragma unroll
            for (int c = 0; c < 4; c++) sc[j][c] = 0.f;

#pragma unroll
        for (int kk8 = 0; kk8 < 16; kk8++) {
            int wb = (kk8 * 8 + 2 * t) ^ swg;
#pragma unroll
            for (int j = 0; j < 8; j++) {
                uint2 bb = *(const uint2*)&Kb[(8 * j + g) * FW + wb];
                mma8(sc[j], qf[kk8][0], qf[kk8][1], qf[kk8][2], qf[kk8][3], bb.x, bb.y);
            }
        }

        float rmax0 = -1e30f, rmax1 = -1e30f;
#pragma unroll
        for (int j = 0; j < 8; j++) {
            int c0 = k0 + 8 * j + 2 * t, c1 = c0 + 1;
            if (c0 >= kend0) sc[j][0] = -1e30f;
            if (c1 >= kend0) sc[j][1] = -1e30f;
            if (c0 >= kend1) sc[j][2] = -1e30f;
            if (c1 >= kend1) sc[j][3] = -1e30f;
            rmax0 = fmaxf(rmax0, fmaxf(sc[j][0], sc[j][1]));
            rmax1 = fmaxf(rmax1, fmaxf(sc[j][2], sc[j][3]));
        }
        rmax0 = fmaxf(rmax0, __shfl_xor_sync(0xffffffffu, rmax0, 1));
        rmax0 = fmaxf(rmax0, __shfl_xor_sync(0xffffffffu, rmax0, 2));
        rmax1 = fmaxf(rmax1, __shfl_xor_sync(0xffffffffu, rmax1, 1));
        rmax1 = fmaxf(rmax1, __shfl_xor_sync(0xffffffffu, rmax1, 2));

        float mn0 = fmaxf(m0v, rmax0), mn1 = fmaxf(m1v, rmax1);
        float al0 = __expf(m0v - mn0), al1 = __expf(m1v - mn1);
        float rs0 = 0.f, rs1 = 0.f;
#pragma unroll
        for (int j = 0; j < 8; j++) {
            float p0 = (sc[j][0] > -5e29f) ? __expf(sc[j][0] - mn0) : 0.f;
            float p1 = (sc[j][1] > -5e29f) ? __expf(sc[j][1] - mn0) : 0.f;
            float p2 = (sc[j][2] > -5e29f) ? __expf(sc[j][2] - mn1) : 0.f;
            float p3 = (sc[j][3] > -5e29f) ? __expf(sc[j][3] - mn1) : 0.f;
            rs0 += p0 + p1;
            rs1 += p2 + p3;
            sc[j][0] = p0; sc[j][1] = p1; sc[j][2] = p2; sc[j][3] = p3;
        }
        rs0 += __shfl_xor_sync(0xffffffffu, rs0, 1);
        rs0 += __shfl_xor_sync(0xffffffffu, rs0, 2);
        rs1 += __shfl_xor_sync(0xffffffffu, rs1, 1);
        rs1 += __shfl_xor_sync(0xffffffffu, rs1, 2);
        l0v = l0v * al0 + rs0;
        l1v = l1v * al1 + rs1;
        m0v = mn0; m1v = mn1;

#pragma unroll
        for (int j = 0; j < 16; j++) {
            O[j][0] *= al0; O[j][1] *= al0;
            O[j][2] *= al1; O[j][3] *= al1;
        }

        const int swv = t << 3;
#pragma unroll
        for (int c = 0; c < 8; c++) {
            uint32_t a0 = f2tf(sc[c][0]);
            uint32_t a1 = f2tf(sc[c][2]);
            uint32_t a2 = f2tf(sc[c][1]);
            uint32_t a3 = f2tf(sc[c][3]);
            const float* v0 = Vb + (8 * c + t) * FW;
            const float* v1 = Vb + (8 * c + t + 4) * FW;
#pragma unroll
            for (int j = 0; j < 16; j++) {
                int wv = (g + 8 * j) ^ swv;
                uint32_t b0 = __float_as_uint(v0[wv]);
                uint32_t b1 = __float_as_uint(v1[wv]);
                mma8(O[j], a0, a1, a2, a3, b0, b1);
            }
        }
    }

    // epilogue: normalize, convert to split-bf16 pairs, write permuted layout
    const int b = bh >> 4;
    const int h = bh & 15;
#pragma unroll
    for (int rr = 0; rr < 2; rr++) {
        int lq = q0 + rowbase + 8 * rr;
        if (lq >= L_) continue;
        float inv = 1.f / (rr ? l1v : l0v);
        size_t rowoff = (size_t)(b * L_ + lq) * KP_;
#pragma unroll
        for (int j = 0; j < 16; j++) {
            float x0 = O[j][2 * rr] * inv;
            float x1 = O[j][2 * rr + 1] * inv;
            uint32_t hp, lp;
            split_pack(x0, x1, hp, lp);
            int p = h * 64 + 4 * j + t;
            int c = pair_perm(p);
            g_aoh[rowoff + c] = hp;
            g_aol[rowoff + c] = lp;
        }
    }
}

// ---------------------------------------------------------------------------
// launch
// ---------------------------------------------------------------------------
extern "C" void kernel_launch(void* const* d_in, const int* in_sizes, int n_in,
                              void* d_out, int out_size)
{
    const float* x    = (const float*)d_in[0];
    const float* Wqkv = (const float*)d_in[1];
    const float* qb   = (const float*)d_in[2];
    const float* vb   = (const float*)d_in[3];
    const float* sml  = (const float*)d_in[4];
    const float* pW   = (const float*)d_in[5];
    const float* pb   = (const float*)d_in[6];
    const float* rope = (const float*)d_in[7];
    float* out = (float*)d_out;

    const size_t qkv_shm   = (size_t)3 * QSTG * sizeof(uint32_t);     // 49,152 B
    const size_t proj_shm  = (size_t)3 * GSTAGE * sizeof(uint32_t);   // 98,304 B
    const size_t flash_shm = (size_t)3 * FSTG * sizeof(float);        // 196,608 B

    cudaFuncSetAttribute(qkv_gemm, cudaFuncAttributeMaxDynamicSharedMemorySize, (int)qkv_shm);
    cudaFuncSetAttribute(proj_gemm, cudaFuncAttributeMaxDynamicSharedMemorySize, (int)proj_shm);
    cudaFuncSetAttribute(flash_attn, cudaFuncAttributeMaxDynamicSharedMemorySize, (int)flash_shm);

    {
        int np;
        np = M_ * KP_;    convert_f16<<<(np + 255) / 256, 256>>>(x, 0, np);
        np = NQKV * KP_;  convert_f16<<<(np + 255) / 256, 256>>>(Wqkv, 1, np);
        np = C_ * KP_;    convert_split_pw<<<(np + 255) / 256, 256>>>(pW, np);
    }

    dim3 g1(NQKV / 128, (M_ + 127) / 128);   // 48 x 40
    qkv_gemm<<<g1, 256, qkv_shm>>>(qb, vb);

    int nwarps = B_ * H_ * L_;
    norm_rope<<<(nwarps + 7) / 8, 256>>>(sml, rope);

    dim3 g3((L_ + 127) / 128, B_ * H_);      // 20 x 32
    flash_attn<<<g3, 256, flash_shm>>>();

    dim3 g4(C_ / 128, (M_ + 127) / 128);     // 16 x 40
    proj_gemm<<<g4, 256, proj_shm>>>(pb, out);
}

// round 14
// speedup vs baseline: 2.7673x; 1.2195x over previous
#include <cuda_runtime.h>
#include <cuda_bf16.h>
#include <cuda_fp16.h>
#include <cstdint>
#include <math.h>

// ---------------------------------------------------------------------------
// Problem constants
// ---------------------------------------------------------------------------
#define B_   2
#define L_   2521
#define C_   2048
#define H_   16
#define HD_  128
#define M_   (B_ * L_)          // 5042
#define K_   2048
#define KP_  1024               // K/2 u32 pairs per row
#define NQKV 6144
#define VL2  1280               // padded key-pairs per (bh, d) row of g_vt

__device__ __constant__ int d_cum[10] = {1, 5, 21, 57, 121, 265, 521, 921, 1497, 2521};

// f32 scratch (plain d-order; intermediates between qkv and norm_rope/transpose)
__device__ float g_q[B_ * H_ * L_ * HD_];
__device__ float g_k[B_ * H_ * L_ * HD_];
__device__ float g_v[B_ * H_ * L_ * HD_];

// fp16 operands
__device__ uint32_t g_xf[M_ * KP_];          // x            (qkv GEMM A)
__device__ uint32_t g_wf[NQKV * KP_];        // W_qkv        (qkv GEMM B)
__device__ uint32_t g_qh[B_ * H_ * L_ * 64]; // q post-rope  (flash A)
__device__ uint32_t g_kh[B_ * H_ * L_ * 64]; // k post-rope  (flash S-B)
__device__ uint32_t g_vt[(size_t)B_ * H_ * HD_ * VL2]; // V^T (flash PV-B)
// split-bf16 operands for proj GEMM
__device__ uint32_t g_pwh[C_ * KP_],  g_pwl[C_ * KP_];
__device__ uint32_t g_aoh[M_ * KP_],  g_aol[M_ * KP_];

// ---------------------------------------------------------------------------
// helpers
// ---------------------------------------------------------------------------
__device__ __forceinline__ uint32_t pack_h2(float lo, float hi) {
    uint32_t r;
    asm("cvt.rn.f16x2.f32 %0, %1, %2;" : "=r"(r) : "f"(hi), "f"(lo));
    return r;
}

__device__ __forceinline__ void mma16bf(float* c,
                                        uint32_t a0, uint32_t a1, uint32_t a2, uint32_t a3,
                                        uint32_t b0, uint32_t b1)
{
    asm volatile(
        "mma.sync.aligned.m16n8k16.row.col.f32.bf16.bf16.f32 "
        "{%0,%1,%2,%3}, {%4,%5,%6,%7}, {%8,%9}, {%0,%1,%2,%3};"
        : "+f"(c[0]), "+f"(c[1]), "+f"(c[2]), "+f"(c[3])
        : "r"(a0), "r"(a1), "r"(a2), "r"(a3), "r"(b0), "r"(b1));
}

__device__ __forceinline__ void mma16f(float* c,
                                       uint32_t a0, uint32_t a1, uint32_t a2, uint32_t a3,
                                       uint32_t b0, uint32_t b1)
{
    asm volatile(
        "mma.sync.aligned.m16n8k16.row.col.f32.f16.f16.f32 "
        "{%0,%1,%2,%3}, {%4,%5,%6,%7}, {%8,%9}, {%0,%1,%2,%3};"
        : "+f"(c[0]), "+f"(c[1]), "+f"(c[2]), "+f"(c[3])
        : "r"(a0), "r"(a1), "r"(a2), "r"(a3), "r"(b0), "r"(b1));
}

__device__ __forceinline__ uint32_t smaddr(const void* p) {
    return (uint32_t)__cvta_generic_to_shared(p);
}
__device__ __forceinline__ void cp16(uint32_t dst, const void* src, bool pred) {
    int sz = pred ? 16 : 0;
    asm volatile("cp.async.cg.shared.global [%0], [%1], 16, %2;"
                 :: "r"(dst), "l"(src), "r"(sz));
}
__device__ __forceinline__ void cp_commit() {
    asm volatile("cp.async.commit_group;");
}
template<int N>
__device__ __forceinline__ void cp_wait() {
    asm volatile("cp.async.wait_group %0;" :: "n"(N));
}

// permuted pair column for mma fragment-order loads (within-8 perm, 16-blocks)
__device__ __forceinline__ int pair_perm(int p) {
    int q = p & 15;
    return (p & ~15) + (q & 8) + (q & 3) * 2 + ((q >> 2) & 1);
}

__device__ __forceinline__ void split_pack(float x0, float x1, uint32_t& hp, uint32_t& lp) {
    __nv_bfloat16 h0 = __float2bfloat16_rn(x0);
    __nv_bfloat16 h1 = __float2bfloat16_rn(x1);
    float l0f = x0 - __bfloat162float(h0);
    float l1f = x1 - __bfloat162float(h1);
    __nv_bfloat16 l0 = __float2bfloat16_rn(l0f);
    __nv_bfloat16 l1 = __float2bfloat16_rn(l1f);
    hp = (uint32_t)__bfloat16_as_ushort(h0) | ((uint32_t)__bfloat16_as_ushort(h1) << 16);
    lp = (uint32_t)__bfloat16_as_ushort(l0) | ((uint32_t)__bfloat16_as_ushort(l1) << 16);
}

// ---------------------------------------------------------------------------
// Kernel 0a: f32 -> fp16 pack (which: 0 = g_xf, 1 = g_wf)
// ---------------------------------------------------------------------------
__global__ void __launch_bounds__(256)
convert_f16(const float* __restrict__ src, int which, int npairs)
{
    int i = blockIdx.x * 256 + threadIdx.x;
    if (i >= npairs) return;
    int row = i >> 10;
    int p = i & 1023;
    float2 v = *(const float2*)(src + (size_t)row * K_ + p * 2);
    uint32_t hp = pack_h2(v.x, v.y);
    uint32_t* dst = (which == 0) ? g_xf : g_wf;
    dst[(size_t)row * KP_ + pair_perm(p)] = hp;
}

__global__ void __launch_bounds__(256)
convert_split_pw(const float* __restrict__ src, int npairs)
{
    int i = blockIdx.x * 256 + threadIdx.x;
    if (i >= npairs) return;
    int row = i >> 10;
    int p = i & 1023;
    float2 v = *(const float2*)(src + (size_t)row * K_ + p * 2);
    uint32_t hp, lp;
    split_pack(v.x, v.y, hp, lp);
    int c = pair_perm(p);
    g_pwh[(size_t)row * KP_ + c] = hp;
    g_pwl[(size_t)row * KP_ + c] = lp;
}

// ---------------------------------------------------------------------------
// Kernel 0c: V f32 [bh][l][d] -> V^T fp16 pairs g_vt[bh][d][keypair slot]
// ---------------------------------------------------------------------------
__global__ void __launch_bounds__(256)
vt_transpose()
{
    int idx = blockIdx.x * 256 + threadIdx.x;
    int d = idx & 127;
    int rest = idx >> 7;
    int kp = rest % VL2;
    int bh = rest / VL2;
    if (bh >= B_ * H_) return;
    int k0 = 2 * kp, k1 = k0 + 1;
    float f0 = (k0 < L_) ? g_v[((size_t)bh * L_ + k0) * HD_ + d] : 0.f;
    float f1 = (k1 < L_) ? g_v[((size_t)bh * L_ + k1) * HD_ + d] : 0.f;
    g_vt[((size_t)bh * HD_ + d) * VL2 + pair_perm(kp)] = pack_h2(f0, f1);
}

// ---------------------------------------------------------------------------
// Single-term fp16 GEMM core (qkv): C[128x128]=A*B^T, BK=32, 3-stage cp.async.
// Epilogue writes q/k/v PLAIN f32 (norm_rope / vt_transpose consume).
// ---------------------------------------------------------------------------
#define GW 16
#define QARR (128 * GW)
#define QSTG (2 * QARR)

__device__ __forceinline__ void qkv_prefetch(
    uint32_t* sbase, const uint32_t* ag, const uint32_t* bg,
    int ku, bool aok, int r, int fq)
{
    int sw = (r & 3) << 2;
    int w0 = (fq ^ sw) * 4;
    int w1 = ((fq + 4) ^ sw) * 4;
    uint32_t dA = smaddr(sbase + r * GW);
    cp16(dA + w0, ag + ku,     aok);
    cp16(dA + w1, ag + ku + 4, aok);
    uint32_t dB = dA + QARR * 4;
    cp16(dB + w0, bg + ku,     true);
    cp16(dB + w1, bg + ku + 4, true);
}

__global__ void __launch_bounds__(256, 2)
qkv_gemm(const float* __restrict__ qb, const float* __restrict__ vb)
{
    extern __shared__ uint32_t smu[];
    float acc[2][8][4];
#pragma unroll
    for (int a = 0; a < 2; a++)
#pragma unroll
        for (int b = 0; b < 8; b++)
#pragma unroll
            for (int c = 0; c < 4; c++) acc[a][b][c] = 0.f;

    const int tid = threadIdx.x;
    const int lane = tid & 31, wid = tid >> 5;
    const int g = lane >> 2, t = lane & 3;
    const int mw = (wid >> 1) * 32, nw = (wid & 1) * 64;
    const int n0 = blockIdx.x * 128;
    const int m0 = blockIdx.y * 128;

    const int r = tid >> 1;
    const int fq = (tid & 1) * 8;
    const bool aok = (m0 + r) < M_;
    const uint32_t* ag = g_xf + (size_t)(aok ? m0 + r : 0) * KP_ + fq;
    const uint32_t* bg = g_wf + (size_t)(n0 + r) * KP_ + fq;

    qkv_prefetch(smu,            ag, bg, 0,  aok, r, fq);
    cp_commit();
    qkv_prefetch(smu + QSTG,     ag, bg, 16, aok, r, fq);
    cp_commit();

    const int swf = (g & 3) << 2;
    const int NIT = KP_ / 16;

    for (int it = 0; it < NIT; it++) {
        if (it + 1 >= NIT) cp_wait<0>(); else cp_wait<1>();
        __syncthreads();
        if (it + 2 < NIT) {
            qkv_prefetch(smu + ((it + 2) % 3) * QSTG, ag, bg, (it + 2) * 16, aok, r, fq);
            cp_commit();
        }

        uint32_t* As = smu + (it % 3) * QSTG;
        uint32_t* Bs = As + QARR;

#pragma unroll
        for (int ks = 0; ks < 2; ks++) {
            const int wb = (ks * 8 + 2 * t) ^ swf;
            uint32_t ah[2][4];
#pragma unroll
            for (int mi = 0; mi < 2; mi++) {
                int r0 = mw + 16 * mi + g;
                uint2 v0 = *(uint2*)&As[r0 * GW + wb];
                uint2 v1 = *(uint2*)&As[(r0 + 8) * GW + wb];
                ah[mi][0] = v0.x; ah[mi][2] = v0.y;
                ah[mi][1] = v1.x; ah[mi][3] = v1.y;
            }
#pragma unroll
            for (int j = 0; j < 8; j++) {
                int cn = nw + 8 * j + g;
                uint2 bh = *(uint2*)&Bs[cn * GW + wb];
#pragma unroll
                for (int mi = 0; mi < 2; mi++)
                    mma16f(acc[mi][j], ah[mi][0], ah[mi][1], ah[mi][2], ah[mi][3], bh.x, bh.y);
            }
        }
    }

    // epilogue: plain f32 writes
    const int tq = n0 >> 11;
    const int h = (n0 & 2047) >> 7;
    float* dst = (tq == 0) ? g_q : ((tq == 1) ? g_k : g_v);

    float2 bias[8];
#pragma unroll
    for (int j = 0; j < 8; j++) {
        int d = nw + 8 * j + 2 * t;
        float b0 = 0.f, b1 = 0.f;
        if (tq == 0) { b0 = qb[h * HD_ + d]; b1 = qb[h * HD_ + d + 1]; }
        else if (tq == 2) { b0 = vb[h * HD_ + d]; b1 = vb[h * HD_ + d + 1]; }
        bias[j] = make_float2(b0, b1);
    }

#pragma unroll
    for (int mi = 0; mi < 2; mi++)
#pragma unroll
        for (int rr = 0; rr < 2; rr++) {
            int gm = m0 + mw + 16 * mi + g + 8 * rr;
            if (gm >= M_) continue;
            int b = gm / L_;
            int l = gm - b * L_;
            float* p = dst + ((size_t)(b * H_ + h) * L_ + l) * HD_;
#pragma unroll
            for (int j = 0; j < 8; j++) {
                float2 o;
                o.x = acc[mi][j][2 * rr] + bias[j].x;
                o.y = acc[mi][j][2 * rr + 1] + bias[j].y;
                *(float2*)(p + nw + 8 * j + 2 * t) = o;
            }
        }
}

// ---------------------------------------------------------------------------
// Kernel 2: norm + rope; writes fp16 pair-permuted q/k (flash operands).
// ---------------------------------------------------------------------------
__global__ void __launch_bounds__(256)
norm_rope(const float* __restrict__ sml, const float* __restrict__ rope)
{
    const int gw = blockIdx.x * 8 + (threadIdx.x >> 5);
    const int lane = threadIdx.x & 31;
    if (gw >= B_ * H_ * L_) return;
    const int l = gw % L_;
    const int h = (gw / L_) % H_;

    float2 cc = *(const float2*)(rope + (size_t)l * 64 + lane * 2);
    float2 ss = *(const float2*)(rope + (size_t)L_ * 64 + (size_t)l * 64 + lane * 2);
    const float scale = __expf(fminf(sml[h], 4.605170185988091f));
    const size_t base = (size_t)gw * HD_ + lane * 4;
    const int s0 = pair_perm(2 * lane);
    const int s1 = pair_perm(2 * lane + 1);

    {
        float4 v = *(const float4*)(g_q + base);
        float ssq = v.x * v.x + v.y * v.y + v.z * v.z + v.w * v.w;
#pragma unroll
        for (int o = 16; o; o >>= 1) ssq += __shfl_xor_sync(0xffffffffu, ssq, o);
        float inv = scale / fmaxf(sqrtf(ssq), 1e-12f);
        v.x *= inv; v.y *= inv; v.z *= inv; v.w *= inv;
        float rx = cc.x * v.x - ss.x * v.y;
        float ry = ss.x * v.x + cc.x * v.y;
        float rz = cc.y * v.z - ss.y * v.w;
        float rw = ss.y * v.z + cc.y * v.w;
        g_qh[(size_t)gw * 64 + s0] = pack_h2(rx, ry);
        g_qh[(size_t)gw * 64 + s1] = pack_h2(rz, rw);
    }
    {
        float4 v = *(const float4*)(g_k + base);
        float ssq = v.x * v.x + v.y * v.y + v.z * v.z + v.w * v.w;
#pragma unroll
        for (int o = 16; o; o >>= 1) ssq += __shfl_xor_sync(0xffffffffu, ssq, o);
        float inv = 1.f / fmaxf(sqrtf(ssq), 1e-12f);
        v.x *= inv; v.y *= inv; v.z *= inv; v.w *= inv;
        float rx = cc.x * v.x - ss.x * v.y;
        float ry = ss.x * v.x + cc.x * v.y;
        float rz = cc.y * v.z - ss.y * v.w;
        float rw = ss.y * v.z + cc.y * v.w;
        g_kh[(size_t)gw * 64 + s0] = pack_h2(rx, ry);
        g_kh[(size_t)gw * 64 + s1] = pack_h2(rz, rw);
    }
}

// ---------------------------------------------------------------------------
// Kernel 3: flash attention, all-fp16 mma (S: QK^T, PV: P from registers).
// K tile: [64 keys][64 u32 pairs] swz (key&7)<<3; Vt tile: [128 d][32 u32]
// swz (d&7)<<2. Q in registers. 3-stage cp.async, one sync/iter.
// ---------------------------------------------------------------------------
#define FKW 64
#define FVW 32
#define KTILE (64 * FKW)           // 4096 u32
#define VTILE (128 * FVW)          // 4096 u32
#define FSTG (KTILE + VTILE)       // 8192 u32 = 32 KB

__device__ __forceinline__ int kend_of(int lq) {
    if (lq >= L_) return 0;
    int ke = 2521;
#pragma unroll
    for (int i = 9; i >= 0; i--)
        if (lq < d_cum[i]) ke = d_cum[i];
    return ke;
}

__device__ __forceinline__ void flash_prefetch(
    uint32_t* sm, int s, int it, const uint32_t* kp, const uint32_t* vtp, int tid)
{
    uint32_t* Kb = sm + s * FSTG;
    uint32_t* Vb = Kb + KTILE;
    const int k0 = it * 64;
    // K: 64 keys x 64 u32
    {
        int kr = tid >> 2;
        int cb = (tid & 3) * 16;
        bool ok = (k0 + kr) < L_;
        const uint32_t* src = kp + (size_t)(ok ? (k0 + kr) : 0) * 64 + cb;
        int sw = (kr & 7) << 3;
        uint32_t d = smaddr(Kb + kr * FKW);
#pragma unroll
        for (int i = 0; i < 4; i++)
            cp16(d + 4 * ((cb + 4 * i) ^ sw), src + 4 * i, ok);
    }
    // Vt: 128 d x 32 u32 (source zero-padded; always valid)
    {
        int dr = tid >> 1;
        int cb = (tid & 1) * 16;
        const uint32_t* src = vtp + (size_t)dr * VL2 + it * 32 + cb;
        int sw = (dr & 7) << 2;
        uint32_t d = smaddr(Vb + dr * FVW);
#pragma unroll
        for (int i = 0; i < 4; i++)
            cp16(d + 4 * ((cb + 4 * i) ^ sw), src + 4 * i, true);
    }
}

__global__ void __launch_bounds__(256, 1)
flash_attn()
{
    extern __shared__ uint32_t smF[];

    const int bh = blockIdx.y;
    const int q0 = (gridDim.x - 1 - blockIdx.x) * 128;
    const uint32_t* qp = g_qh + (size_t)bh * L_ * 64;
    const uint32_t* kp = g_kh + (size_t)bh * L_ * 64;
    const uint32_t* vtp = g_vt + (size_t)bh * HD_ * VL2;
    const int tid = threadIdx.x, lane = tid & 31, wid = tid >> 5;
    const int g = lane >> 2, t = lane & 3;
    const int rowbase = wid * 16 + g;

    int kmax;
    {
        int lql = min(q0 + 127, L_ - 1);
        kmax = 2521;
#pragma unroll
        for (int i = 9; i >= 0; i--)
            if (lql < d_cum[i]) kmax = d_cum[i];
    }
    const int niter = (kmax + 63) / 64;

    // stage Q (128 rows x 64 u32 = one stage) into stage 0
    {
        int r = tid >> 1;
        int cb = (tid & 1) * 32;
        bool ok = (q0 + r) < L_;
        const uint32_t* src = qp + (size_t)(ok ? (q0 + r) : 0) * 64 + cb;
        int sw = (r & 7) << 3;
        uint32_t d = smaddr(smF + r * FKW);
#pragma unroll
        for (int i = 0; i < 8; i++)
            cp16(d + 4 * ((cb + 4 * i) ^ sw), src + 4 * i, ok);
    }
    cp_commit();
    flash_prefetch(smF, 1, 0, kp, vtp, tid);
    cp_commit();
    if (niter > 1) flash_prefetch(smF, 2, 1, kp, vtp, tid);
    cp_commit();

    cp_wait<2>();       // Q landed
    __syncthreads();

    uint32_t qf[8][4];
    {
        const int swq = g << 3;      // rowbase&7 == g
#pragma unroll
        for (int c = 0; c < 8; c++) {
            int wb = (c * 8 + 2 * t) ^ swq;
            uint2 a0 = *(const uint2*)&smF[rowbase * FKW + wb];
            uint2 a1 = *(const uint2*)&smF[(rowbase + 8) * FKW + wb];
            qf[c][0] = a0.x; qf[c][2] = a0.y;
            qf[c][1] = a1.x; qf[c][3] = a1.y;
        }
    }
    __syncthreads();

    const int kend0 = kend_of(q0 + rowbase);
    const int kend1 = kend_of(q0 + rowbase + 8);

    float m0v = -1e30f, m1v = -1e30f, l0v = 0.f, l1v = 0.f;
    float O[16][4];
#pragma unroll
    for (int j = 0; j < 16; j++)
#pragma unroll
        for (int c = 0; c < 4; c++) O[j][c] = 0.f;

    for (int it = 0; it < niter; it++) {
        const int k0 = it * 64;
        if (it + 1 >= niter) cp_wait<0>(); else cp_wait<1>();
        __syncthreads();
        if (it + 2 < niter) {
            flash_prefetch(smF, it % 3, it + 2, kp, vtp, tid);
            cp_commit();
        }

        uint32_t* Kb = smF + ((it + 1) % 3) * FSTG;
        uint32_t* Vt = Kb + KTILE;

        // S = Q K^T  (8 k16-chunks over d=128, 8 n-tiles over 64 keys)
        float sc[8][4];
#pragma unroll
        for (int j = 0; j < 8; j++)
#pragma unroll
            for (int c = 0; c < 4; c++) sc[j][c] = 0.f;

        const int swk = g << 3;
#pragma unroll
        for (int c = 0; c < 8; c++) {
            int wb = (c * 8 + 2 * t) ^ swk;
#pragma unroll
            for (int j = 0; j < 8; j++) {
                uint2 bb = *(const uint2*)&Kb[(8 * j + g) * FKW + wb];
                mma16f(sc[j], qf[c][0], qf[c][1], qf[c][2], qf[c][3], bb.x, bb.y);
            }
        }

        // mask + online softmax (layout identical to before)
        float rmax0 = -1e30f, rmax1 = -1e30f;
#pragma unroll
        for (int j = 0; j < 8; j++) {
            int c0 = k0 + 8 * j + 2 * t, c1 = c0 + 1;
            if (c0 >= kend0) sc[j][0] = -1e30f;
            if (c1 >= kend0) sc[j][1] = -1e30f;
            if (c0 >= kend1) sc[j][2] = -1e30f;
            if (c1 >= kend1) sc[j][3] = -1e30f;
            rmax0 = fmaxf(rmax0, fmaxf(sc[j][0], sc[j][1]));
            rmax1 = fmaxf(rmax1, fmaxf(sc[j][2], sc[j][3]));
        }
        rmax0 = fmaxf(rmax0, __shfl_xor_sync(0xffffffffu, rmax0, 1));
        rmax0 = fmaxf(rmax0, __shfl_xor_sync(0xffffffffu, rmax0, 2));
        rmax1 = fmaxf(rmax1, __shfl_xor_sync(0xffffffffu, rmax1, 1));
        rmax1 = fmaxf(rmax1, __shfl_xor_sync(0xffffffffu, rmax1, 2));

        float mn0 = fmaxf(m0v, rmax0), mn1 = fmaxf(m1v, rmax1);
        float al0 = __expf(m0v - mn0), al1 = __expf(m1v - mn1);
        float rs0 = 0.f, rs1 = 0.f;
#pragma unroll
        for (int j = 0; j < 8; j++) {
            float p0 = (sc[j][0] > -5e29f) ? __expf(sc[j][0] - mn0) : 0.f;
            float p1 = (sc[j][1] > -5e29f) ? __expf(sc[j][1] - mn0) : 0.f;
            float p2 = (sc[j][2] > -5e29f) ? __expf(sc[j][2] - mn1) : 0.f;
            float p3 = (sc[j][3] > -5e29f) ? __expf(sc[j][3] - mn1) : 0.f;
            rs0 += p0 + p1;
            rs1 += p2 + p3;
            sc[j][0] = p0; sc[j][1] = p1; sc[j][2] = p2; sc[j][3] = p3;
        }
        rs0 += __shfl_xor_sync(0xffffffffu, rs0, 1);
        rs0 += __shfl_xor_sync(0xffffffffu, rs0, 2);
        rs1 += __shfl_xor_sync(0xffffffffu, rs1, 1);
        rs1 += __shfl_xor_sync(0xffffffffu, rs1, 2);
        l0v = l0v * al0 + rs0;
        l1v = l1v * al1 + rs1;
        m0v = mn0; m1v = mn1;

#pragma unroll
        for (int j = 0; j < 16; j++) {
            O[j][0] *= al0; O[j][1] *= al0;
            O[j][2] *= al1; O[j][3] *= al1;
        }

        // O += P V : P packed straight from sc (4 k16-chunks over 64 keys)
        const int swv = g << 2;
#pragma unroll
        for (int c = 0; c < 4; c++) {
            uint32_t a0 = pack_h2(sc[2 * c][0],     sc[2 * c][1]);
            uint32_t a1 = pack_h2(sc[2 * c][2],     sc[2 * c][3]);
            uint32_t a2 = pack_h2(sc[2 * c + 1][0], sc[2 * c + 1][1]);
            uint32_t a3 = pack_h2(sc[2 * c + 1][2], sc[2 * c + 1][3]);
            int wv = (c * 8 + 2 * t) ^ swv;
#pragma unroll
            for (int j = 0; j < 16; j++) {
                uint2 bb = *(const uint2*)&Vt[(8 * j + g) * FVW + wv];
                mma16f(O[j], a0, a1, a2, a3, bb.x, bb.y);
            }
        }
    }

    // epilogue: normalize, split-bf16 pairs, pair-permuted g_ao (proj operand)
    const int b = bh >> 4;
    const int h = bh & 15;
#pragma unroll
    for (int rr = 0; rr < 2; rr++) {
        int lq = q0 + rowbase + 8 * rr;
        if (lq >= L_) continue;
        float inv = 1.f / (rr ? l1v : l0v);
        size_t rowoff = (size_t)(b * L_ + lq) * KP_;
#pragma unroll
        for (int j = 0; j < 16; j++) {
            float x0 = O[j][2 * rr] * inv;
            float x1 = O[j][2 * rr + 1] * inv;
            uint32_t hp, lp;
            split_pack(x0, x1, hp, lp);
            int p = h * 64 + 4 * j + t;
            int c = pair_perm(p);
            g_aoh[rowoff + c] = hp;
            g_aol[rowoff + c] = lp;
        }
    }
}

// ---------------------------------------------------------------------------
// split-bf16 GEMM (proj, unchanged from R13)
// ---------------------------------------------------------------------------
#define GARR (128 * GW)
#define GSTAGE (4 * GARR)

__device__ __forceinline__ void gemm_prefetch(
    uint32_t* sbase, const uint32_t* agh, const uint32_t* agl,
    const uint32_t* bgh, const uint32_t* bgl, int ku, bool aok, int r, int fq)
{
    int sw = (r & 3) << 2;
    int w0 = ((fq ^ sw)) * 4;
    int w1 = (((fq + 4) ^ sw)) * 4;
    uint32_t dA = smaddr(sbase + r * GW);
    cp16(dA + w0, agh + ku,     aok);
    cp16(dA + w1, agh + ku + 4, aok);
    uint32_t dAl = dA + GARR * 4;
    cp16(dAl + w0, agl + ku,     aok);
    cp16(dAl + w1, agl + ku + 4, aok);
    uint32_t dB = dAl + GARR * 4;
    cp16(dB + w0, bgh + ku,     true);
    cp16(dB + w1, bgh + ku + 4, true);
    uint32_t dBl = dB + GARR * 4;
    cp16(dBl + w0, bgl + ku,     true);
    cp16(dBl + w1, bgl + ku + 4, true);
}

__global__ void __launch_bounds__(256, 2)
proj_gemm(const float* __restrict__ pb, float* __restrict__ out)
{
    extern __shared__ uint32_t smu[];
    float acc[2][8][4];
#pragma unroll
    for (int a = 0; a < 2; a++)
#pragma unroll
        for (int b = 0; b < 8; b++)
#pragma unroll
            for (int c = 0; c < 4; c++) acc[a][b][c] = 0.f;

    const int tid = threadIdx.x;
    const int lane = tid & 31, wid = tid >> 5;
    const int g = lane >> 2, t = lane & 3;
    const int mw = (wid >> 1) * 32, nw = (wid & 1) * 64;
    const int n0 = blockIdx.x * 128;
    const int m0 = blockIdx.y * 128;

    const int r = tid >> 1;
    const int fq = (tid & 1) * 8;
    const bool aok = (m0 + r) < M_;
    const int arow = aok ? (m0 + r) : 0;
    const uint32_t* agh = g_aoh + (size_t)arow * KP_ + fq;
    const uint32_t* agl = g_aol + (size_t)arow * KP_ + fq;
    const uint32_t* bgh = g_pwh + (size_t)(n0 + r) * KP_ + fq;
    const uint32_t* bgl = g_pwl + (size_t)(n0 + r) * KP_ + fq;

    gemm_prefetch(smu,              agh, agl, bgh, bgl, 0,  aok, r, fq);
    cp_commit();
    gemm_prefetch(smu + GSTAGE,     agh, agl, bgh, bgl, 16, aok, r, fq);
    cp_commit();

    const int swf = (g & 3) << 2;
    const int NIT = KP_ / 16;

    for (int it = 0; it < NIT; it++) {
        if (it + 1 >= NIT) cp_wait<0>(); else cp_wait<1>();
        __syncthreads();
        if (it + 2 < NIT) {
            gemm_prefetch(smu + ((it + 2) % 3) * GSTAGE, agh, agl, bgh, bgl,
                          (it + 2) * 16, aok, r, fq);
            cp_commit();
        }

        uint32_t* Ah = smu + (it % 3) * GSTAGE;
        uint32_t* Al = Ah + GARR;
        uint32_t* Bh = Al + GARR;
        uint32_t* Bl = Bh + GARR;

#pragma unroll
        for (int ks = 0; ks < 2; ks++) {
            const int wb = (ks * 8 + 2 * t) ^ swf;
            uint32_t ah[2][4], al[2][4];
#pragma unroll
            for (int mi = 0; mi < 2; mi++) {
                int r0 = mw + 16 * mi + g;
                uint2 v0 = *(uint2*)&Ah[r0 * GW + wb];
                uint2 v1 = *(uint2*)&Ah[(r0 + 8) * GW + wb];
                ah[mi][0] = v0.x; ah[mi][2] = v0.y;
                ah[mi][1] = v1.x; ah[mi][3] = v1.y;
                uint2 w0 = *(uint2*)&Al[r0 * GW + wb];
                uint2 w1 = *(uint2*)&Al[(r0 + 8) * GW + wb];
                al[mi][0] = w0.x; al[mi][2] = w0.y;
                al[mi][1] = w1.x; al[mi][3] = w1.y;
            }
#pragma unroll
            for (int j = 0; j < 8; j++) {
                int cn = nw + 8 * j + g;
                uint2 bh = *(uint2*)&Bh[cn * GW + wb];
                uint2 bl = *(uint2*)&Bl[cn * GW + wb];
#pragma unroll
                for (int mi = 0; mi < 2; mi++) {
                    mma16bf(acc[mi][j], ah[mi][0], ah[mi][1], ah[mi][2], ah[mi][3], bh.x, bh.y);
                    mma16bf(acc[mi][j], ah[mi][0], ah[mi][1], ah[mi][2], ah[mi][3], bl.x, bl.y);
                    mma16bf(acc[mi][j], al[mi][0], al[mi][1], al[mi][2], al[mi][3], bh.x, bh.y);
                }
            }
        }
    }

    float2 bias[8];
#pragma unroll
    for (int j = 0; j < 8; j++) {
        int n = n0 + nw + 8 * j + 2 * t;
        bias[j] = make_float2(pb[n], pb[n + 1]);
    }

#pragma unroll
    for (int mi = 0; mi < 2; mi++)
#pragma unroll
        for (int rr = 0; rr < 2; rr++) {
            int gm = m0 + mw + 16 * mi + g + 8 * rr;
            if (gm >= M_) continue;
            float* p = out + (size_t)gm * C_ + n0 + nw;
#pragma unroll
            for (int j = 0; j < 8; j++) {
                float2 o;
                o.x = acc[mi][j][2 * rr] + bias[j].x;
                o.y = acc[mi][j][2 * rr + 1] + bias[j].y;
                *(float2*)(p + 8 * j + 2 * t) = o;
            }
        }
}

// ---------------------------------------------------------------------------
// launch
// ---------------------------------------------------------------------------
extern "C" void kernel_launch(void* const* d_in, const int* in_sizes, int n_in,
                              void* d_out, int out_size)
{
    const float* x    = (const float*)d_in[0];
    const float* Wqkv = (const float*)d_in[1];
    const float* qb   = (const float*)d_in[2];
    const float* vb   = (const float*)d_in[3];
    const float* sml  = (const float*)d_in[4];
    const float* pW   = (const float*)d_in[5];
    const float* pb   = (const float*)d_in[6];
    const float* rope = (const float*)d_in[7];
    float* out = (float*)d_out;

    const size_t qkv_shm   = (size_t)3 * QSTG * sizeof(uint32_t);     // 49,152 B
    const size_t proj_shm  = (size_t)3 * GSTAGE * sizeof(uint32_t);   // 98,304 B
    const size_t flash_shm = (size_t)3 * FSTG * sizeof(uint32_t);     // 98,304 B

    cudaFuncSetAttribute(qkv_gemm, cudaFuncAttributeMaxDynamicSharedMemorySize, (int)qkv_shm);
    cudaFuncSetAttribute(proj_gemm, cudaFuncAttributeMaxDynamicSharedMemorySize, (int)proj_shm);
    cudaFuncSetAttribute(flash_attn, cudaFuncAttributeMaxDynamicSharedMemorySize, (int)flash_shm);

    {
        int np;
        np = M_ * KP_;    convert_f16<<<(np + 255) / 256, 256>>>(x, 0, np);
        np = NQKV * KP_;  convert_f16<<<(np + 255) / 256, 256>>>(Wqkv, 1, np);
        np = C_ * KP_;    convert_split_pw<<<(np + 255) / 256, 256>>>(pW, np);
    }

    dim3 g1(NQKV / 128, (M_ + 127) / 128);   // 48 x 40
    qkv_gemm<<<g1, 256, qkv_shm>>>(qb, vb);

    int nwarps = B_ * H_ * L_;
    norm_rope<<<(nwarps + 7) / 8, 256>>>(sml, rope);

    {
        int nth = B_ * H_ * VL2 * HD_;       // 5,242,880
        vt_transpose<<<(nth + 255) / 256, 256>>>();
    }

    dim3 g3((L_ + 127) / 128, B_ * H_);      // 20 x 32
    flash_attn<<<g3, 256, flash_shm>>>();

    dim3 g4(C_ / 128, (M_ + 127) / 128);     // 16 x 40
    proj_gemm<<<g4, 256, proj_shm>>>(pb, out);
}

// round 15
// speedup vs baseline: 3.4134x; 1.2334x over previous
#include <cuda_runtime.h>
#include <cuda_bf16.h>
#include <cuda_fp16.h>
#include <cstdint>
#include <math.h>

// ---------------------------------------------------------------------------
// Problem constants
// ---------------------------------------------------------------------------
#define B_   2
#define L_   2521
#define C_   2048
#define H_   16
#define HD_  128
#define M_   (B_ * L_)          // 5042
#define K_   2048
#define KP_  1024               // K/2 u32 pairs per row
#define NQKV 6144
#define VL2  1280               // padded key-pairs per (bh, d) row of g_vt

__device__ __constant__ int d_cum[10] = {1, 5, 21, 57, 121, 265, 521, 921, 1497, 2521};

// f32 scratch (plain d-order)
__device__ float g_q[B_ * H_ * L_ * HD_];
__device__ float g_k[B_ * H_ * L_ * HD_];
__device__ float g_v[B_ * H_ * L_ * HD_];

// fp16 operands (u32 = packed half2, pair-permuted)
__device__ uint32_t g_xf[M_ * KP_];          // x            (qkv A)
__device__ uint32_t g_wf[NQKV * KP_];        // W_qkv        (qkv B)
__device__ uint32_t g_qh[B_ * H_ * L_ * 64]; // q post-rope  (flash A)
__device__ uint32_t g_kh[B_ * H_ * L_ * 64]; // k post-rope  (flash S-B)
__device__ uint32_t g_vt[(size_t)B_ * H_ * HD_ * VL2]; // V^T (flash PV-B)
__device__ uint32_t g_aof[M_ * KP_];         // attn out     (proj A)
__device__ uint32_t g_pwf[C_ * KP_];         // proj_W       (proj B)

// ---------------------------------------------------------------------------
// helpers
// ---------------------------------------------------------------------------
__device__ __forceinline__ uint32_t pack_h2(float lo, float hi) {
    uint32_t r;
    asm("cvt.rn.f16x2.f32 %0, %1, %2;" : "=r"(r) : "f"(hi), "f"(lo));
    return r;
}

__device__ __forceinline__ void mma16f(float* c,
                                       uint32_t a0, uint32_t a1, uint32_t a2, uint32_t a3,
                                       uint32_t b0, uint32_t b1)
{
    asm volatile(
        "mma.sync.aligned.m16n8k16.row.col.f32.f16.f16.f32 "
        "{%0,%1,%2,%3}, {%4,%5,%6,%7}, {%8,%9}, {%0,%1,%2,%3};"
        : "+f"(c[0]), "+f"(c[1]), "+f"(c[2]), "+f"(c[3])
        : "r"(a0), "r"(a1), "r"(a2), "r"(a3), "r"(b0), "r"(b1));
}

__device__ __forceinline__ uint32_t smaddr(const void* p) {
    return (uint32_t)__cvta_generic_to_shared(p);
}
__device__ __forceinline__ void cp16(uint32_t dst, const void* src, bool pred) {
    int sz = pred ? 16 : 0;
    asm volatile("cp.async.cg.shared.global [%0], [%1], 16, %2;"
                 :: "r"(dst), "l"(src), "r"(sz));
}
__device__ __forceinline__ void cp_commit() {
    asm volatile("cp.async.commit_group;");
}
template<int N>
__device__ __forceinline__ void cp_wait() {
    asm volatile("cp.async.wait_group %0;" :: "n"(N));
}

__device__ __forceinline__ int pair_perm(int p) {
    int q = p & 15;
    return (p & ~15) + (q & 8) + (q & 3) * 2 + ((q >> 2) & 1);
}

// ---------------------------------------------------------------------------
// Kernel 0: f32 -> fp16 pack (which: 0 = g_xf, 1 = g_wf, 2 = g_pwf)
// ---------------------------------------------------------------------------
__global__ void __launch_bounds__(256)
convert_f16(const float* __restrict__ src, int which, int npairs)
{
    int i = blockIdx.x * 256 + threadIdx.x;
    if (i >= npairs) return;
    int row = i >> 10;
    int p = i & 1023;
    float2 v = *(const float2*)(src + (size_t)row * K_ + p * 2);
    uint32_t hp = pack_h2(v.x, v.y);
    uint32_t* dst = (which == 0) ? g_xf : (which == 1) ? g_wf : g_pwf;
    dst[(size_t)row * KP_ + pair_perm(p)] = hp;
}

// ---------------------------------------------------------------------------
// Kernel 0c: V f32 -> V^T fp16 pairs g_vt[bh][d][keypair slot]
// ---------------------------------------------------------------------------
__global__ void __launch_bounds__(256)
vt_transpose()
{
    int idx = blockIdx.x * 256 + threadIdx.x;
    int d = idx & 127;
    int rest = idx >> 7;
    int kp = rest % VL2;
    int bh = rest / VL2;
    if (bh >= B_ * H_) return;
    int k0 = 2 * kp, k1 = k0 + 1;
    float f0 = (k0 < L_) ? g_v[((size_t)bh * L_ + k0) * HD_ + d] : 0.f;
    float f1 = (k1 < L_) ? g_v[((size_t)bh * L_ + k1) * HD_ + d] : 0.f;
    g_vt[((size_t)bh * HD_ + d) * VL2 + pair_perm(kp)] = pack_h2(f0, f1);
}

// ---------------------------------------------------------------------------
// Single-term fp16 GEMM mainloop (shared by qkv and proj).
// C[128x128]=A*B^T, BK=32, 3-stage cp.async, XOR swizzle, 2 CTAs/SM.
// ---------------------------------------------------------------------------
#define GW 16
#define QARR (128 * GW)
#define QSTG (2 * QARR)

__device__ __forceinline__ void f16_prefetch(
    uint32_t* sbase, const uint32_t* ag, const uint32_t* bg,
    int ku, bool aok, int r, int fq)
{
    int sw = (r & 3) << 2;
    int w0 = (fq ^ sw) * 4;
    int w1 = ((fq + 4) ^ sw) * 4;
    uint32_t dA = smaddr(sbase + r * GW);
    cp16(dA + w0, ag + ku,     aok);
    cp16(dA + w1, ag + ku + 4, aok);
    uint32_t dB = dA + QARR * 4;
    cp16(dB + w0, bg + ku,     true);
    cp16(dB + w1, bg + ku + 4, true);
}

__device__ __forceinline__ void f16_core(
    const uint32_t* __restrict__ Ag, const uint32_t* __restrict__ Bg,
    int m0, int n0, uint32_t* smu, float acc[2][8][4], int tid)
{
    const int lane = tid & 31, wid = tid >> 5;
    const int g = lane >> 2, t = lane & 3;
    const int mw = (wid >> 1) * 32, nw = (wid & 1) * 64;

    const int r = tid >> 1;
    const int fq = (tid & 1) * 8;
    const bool aok = (m0 + r) < M_;
    const uint32_t* ag = Ag + (size_t)(aok ? m0 + r : 0) * KP_ + fq;
    const uint32_t* bg = Bg + (size_t)(n0 + r) * KP_ + fq;

    f16_prefetch(smu,            ag, bg, 0,  aok, r, fq);
    cp_commit();
    f16_prefetch(smu + QSTG,     ag, bg, 16, aok, r, fq);
    cp_commit();

    const int swf = (g & 3) << 2;
    const int NIT = KP_ / 16;

    for (int it = 0; it < NIT; it++) {
        if (it + 1 >= NIT) cp_wait<0>(); else cp_wait<1>();
        __syncthreads();
        if (it + 2 < NIT) {
            f16_prefetch(smu + ((it + 2) % 3) * QSTG, ag, bg, (it + 2) * 16, aok, r, fq);
            cp_commit();
        }

        uint32_t* As = smu + (it % 3) * QSTG;
        uint32_t* Bs = As + QARR;

#pragma unroll
        for (int ks = 0; ks < 2; ks++) {
            const int wb = (ks * 8 + 2 * t) ^ swf;
            uint32_t ah[2][4];
#pragma unroll
            for (int mi = 0; mi < 2; mi++) {
                int r0 = mw + 16 * mi + g;
                uint2 v0 = *(uint2*)&As[r0 * GW + wb];
                uint2 v1 = *(uint2*)&As[(r0 + 8) * GW + wb];
                ah[mi][0] = v0.x; ah[mi][2] = v0.y;
                ah[mi][1] = v1.x; ah[mi][3] = v1.y;
            }
#pragma unroll
            for (int j = 0; j < 8; j++) {
                int cn = nw + 8 * j + g;
                uint2 bh = *(uint2*)&Bs[cn * GW + wb];
#pragma unroll
                for (int mi = 0; mi < 2; mi++)
                    mma16f(acc[mi][j], ah[mi][0], ah[mi][1], ah[mi][2], ah[mi][3], bh.x, bh.y);
            }
        }
    }
}

// ---------------------------------------------------------------------------
// Kernel 1: QKV GEMM + scatter epilogue (plain f32 q/k/v)
// ---------------------------------------------------------------------------
__global__ void __launch_bounds__(256, 2)
qkv_gemm(const float* __restrict__ qb, const float* __restrict__ vb)
{
    extern __shared__ uint32_t smu[];
    float acc[2][8][4];
#pragma unroll
    for (int a = 0; a < 2; a++)
#pragma unroll
        for (int b = 0; b < 8; b++)
#pragma unroll
            for (int c = 0; c < 4; c++) acc[a][b][c] = 0.f;

    const int tid = threadIdx.x;
    const int lane = tid & 31, wid = tid >> 5;
    const int g = lane >> 2, t = lane & 3;
    const int mw = (wid >> 1) * 32, nw = (wid & 1) * 64;
    const int n0 = blockIdx.x * 128;
    const int m0 = blockIdx.y * 128;

    f16_core(g_xf, g_wf, m0, n0, smu, acc, tid);

    const int tq = n0 >> 11;
    const int h = (n0 & 2047) >> 7;
    float* dst = (tq == 0) ? g_q : ((tq == 1) ? g_k : g_v);

    float2 bias[8];
#pragma unroll
    for (int j = 0; j < 8; j++) {
        int d = nw + 8 * j + 2 * t;
        float b0 = 0.f, b1 = 0.f;
        if (tq == 0) { b0 = qb[h * HD_ + d]; b1 = qb[h * HD_ + d + 1]; }
        else if (tq == 2) { b0 = vb[h * HD_ + d]; b1 = vb[h * HD_ + d + 1]; }
        bias[j] = make_float2(b0, b1);
    }

#pragma unroll
    for (int mi = 0; mi < 2; mi++)
#pragma unroll
        for (int rr = 0; rr < 2; rr++) {
            int gm = m0 + mw + 16 * mi + g + 8 * rr;
            if (gm >= M_) continue;
            int b = gm / L_;
            int l = gm - b * L_;
            float* p = dst + ((size_t)(b * H_ + h) * L_ + l) * HD_;
#pragma unroll
            for (int j = 0; j < 8; j++) {
                float2 o;
                o.x = acc[mi][j][2 * rr] + bias[j].x;
                o.y = acc[mi][j][2 * rr + 1] + bias[j].y;
                *(float2*)(p + nw + 8 * j + 2 * t) = o;
            }
        }
}

// ---------------------------------------------------------------------------
// Kernel 4: proj GEMM (single-term fp16) + bias epilogue
// ---------------------------------------------------------------------------
__global__ void __launch_bounds__(256, 2)
proj_gemm(const float* __restrict__ pb, float* __restrict__ out)
{
    extern __shared__ uint32_t smu[];
    float acc[2][8][4];
#pragma unroll
    for (int a = 0; a < 2; a++)
#pragma unroll
        for (int b = 0; b < 8; b++)
#pragma unroll
            for (int c = 0; c < 4; c++) acc[a][b][c] = 0.f;

    const int tid = threadIdx.x;
    const int lane = tid & 31, wid = tid >> 5;
    const int g = lane >> 2, t = lane & 3;
    const int mw = (wid >> 1) * 32, nw = (wid & 1) * 64;
    const int n0 = blockIdx.x * 128;
    const int m0 = blockIdx.y * 128;

    f16_core(g_aof, g_pwf, m0, n0, smu, acc, tid);

    float2 bias[8];
#pragma unroll
    for (int j = 0; j < 8; j++) {
        int n = n0 + nw + 8 * j + 2 * t;
        bias[j] = make_float2(pb[n], pb[n + 1]);
    }

#pragma unroll
    for (int mi = 0; mi < 2; mi++)
#pragma unroll
        for (int rr = 0; rr < 2; rr++) {
            int gm = m0 + mw + 16 * mi + g + 8 * rr;
            if (gm >= M_) continue;
            float* p = out + (size_t)gm * C_ + n0 + nw;
#pragma unroll
            for (int j = 0; j < 8; j++) {
                float2 o;
                o.x = acc[mi][j][2 * rr] + bias[j].x;
                o.y = acc[mi][j][2 * rr + 1] + bias[j].y;
                *(float2*)(p + 8 * j + 2 * t) = o;
            }
        }
}

// ---------------------------------------------------------------------------
// Kernel 2: norm + rope; writes fp16 pair-permuted q/k
// ---------------------------------------------------------------------------
__global__ void __launch_bounds__(256)
norm_rope(const float* __restrict__ sml, const float* __restrict__ rope)
{
    const int gw = blockIdx.x * 8 + (threadIdx.x >> 5);
    const int lane = threadIdx.x & 31;
    if (gw >= B_ * H_ * L_) return;
    const int l = gw % L_;
    const int h = (gw / L_) % H_;

    float2 cc = *(const float2*)(rope + (size_t)l * 64 + lane * 2);
    float2 ss = *(const float2*)(rope + (size_t)L_ * 64 + (size_t)l * 64 + lane * 2);
    const float scale = __expf(fminf(sml[h], 4.605170185988091f));
    const size_t base = (size_t)gw * HD_ + lane * 4;
    const int s0 = pair_perm(2 * lane);
    const int s1 = pair_perm(2 * lane + 1);

    {
        float4 v = *(const float4*)(g_q + base);
        float ssq = v.x * v.x + v.y * v.y + v.z * v.z + v.w * v.w;
#pragma unroll
        for (int o = 16; o; o >>= 1) ssq += __shfl_xor_sync(0xffffffffu, ssq, o);
        float inv = scale / fmaxf(sqrtf(ssq), 1e-12f);
        v.x *= inv; v.y *= inv; v.z *= inv; v.w *= inv;
        float rx = cc.x * v.x - ss.x * v.y;
        float ry = ss.x * v.x + cc.x * v.y;
        float rz = cc.y * v.z - ss.y * v.w;
        float rw = ss.y * v.z + cc.y * v.w;
        g_qh[(size_t)gw * 64 + s0] = pack_h2(rx, ry);
        g_qh[(size_t)gw * 64 + s1] = pack_h2(rz, rw);
    }
    {
        float4 v = *(const float4*)(g_k + base);
        float ssq = v.x * v.x + v.y * v.y + v.z * v.z + v.w * v.w;
#pragma unroll
        for (int o = 16; o; o >>= 1) ssq += __shfl_xor_sync(0xffffffffu, ssq, o);
        float inv = 1.f / fmaxf(sqrtf(ssq), 1e-12f);
        v.x *= inv; v.y *= inv; v.z *= inv; v.w *= inv;
        float rx = cc.x * v.x - ss.x * v.y;
        float ry = ss.x * v.x + cc.x * v.y;
        float rz = cc.y * v.z - ss.y * v.w;
        float rw = ss.y * v.z + cc.y * v.w;
        g_kh[(size_t)gw * 64 + s0] = pack_h2(rx, ry);
        g_kh[(size_t)gw * 64 + s1] = pack_h2(rz, rw);
    }
}

// ---------------------------------------------------------------------------
// Kernel 3: flash attention, all-fp16 mma (unchanged from R14 except epilogue
// writes g_aof as single fp16 pair store).
// ---------------------------------------------------------------------------
#define FKW 64
#define FVW 32
#define KTILE (64 * FKW)
#define VTILE (128 * FVW)
#define FSTG (KTILE + VTILE)

__device__ __forceinline__ int kend_of(int lq) {
    if (lq >= L_) return 0;
    int ke = 2521;
#pragma unroll
    for (int i = 9; i >= 0; i--)
        if (lq < d_cum[i]) ke = d_cum[i];
    return ke;
}

__device__ __forceinline__ void flash_prefetch(
    uint32_t* sm, int s, int it, const uint32_t* kp, const uint32_t* vtp, int tid)
{
    uint32_t* Kb = sm + s * FSTG;
    uint32_t* Vb = Kb + KTILE;
    const int k0 = it * 64;
    {
        int kr = tid >> 2;
        int cb = (tid & 3) * 16;
        bool ok = (k0 + kr) < L_;
        const uint32_t* src = kp + (size_t)(ok ? (k0 + kr) : 0) * 64 + cb;
        int sw = (kr & 7) << 3;
        uint32_t d = smaddr(Kb + kr * FKW);
#pragma unroll
        for (int i = 0; i < 4; i++)
            cp16(d + 4 * ((cb + 4 * i) ^ sw), src + 4 * i, ok);
    }
    {
        int dr = tid >> 1;
        int cb = (tid & 1) * 16;
        const uint32_t* src = vtp + (size_t)dr * VL2 + it * 32 + cb;
        int sw = (dr & 7) << 2;
        uint32_t d = smaddr(Vb + dr * FVW);
#pragma unroll
        for (int i = 0; i < 4; i++)
            cp16(d + 4 * ((cb + 4 * i) ^ sw), src + 4 * i, true);
    }
}

__global__ void __launch_bounds__(256, 1)
flash_attn()
{
    extern __shared__ uint32_t smF[];

    const int bh = blockIdx.y;
    const int q0 = (gridDim.x - 1 - blockIdx.x) * 128;
    const uint32_t* qp = g_qh + (size_t)bh * L_ * 64;
    const uint32_t* kp = g_kh + (size_t)bh * L_ * 64;
    const uint32_t* vtp = g_vt + (size_t)bh * HD_ * VL2;
    const int tid = threadIdx.x, lane = tid & 31, wid = tid >> 5;
    const int g = lane >> 2, t = lane & 3;
    const int rowbase = wid * 16 + g;

    int kmax;
    {
        int lql = min(q0 + 127, L_ - 1);
        kmax = 2521;
#pragma unroll
        for (int i = 9; i >= 0; i--)
            if (lql < d_cum[i]) kmax = d_cum[i];
    }
    const int niter = (kmax + 63) / 64;

    {
        int r = tid >> 1;
        int cb = (tid & 1) * 32;
        bool ok = (q0 + r) < L_;
        const uint32_t* src = qp + (size_t)(ok ? (q0 + r) : 0) * 64 + cb;
        int sw = (r & 7) << 3;
        uint32_t d = smaddr(smF + r * FKW);
#pragma unroll
        for (int i = 0; i < 8; i++)
            cp16(d + 4 * ((cb + 4 * i) ^ sw), src + 4 * i, ok);
    }
    cp_commit();
    flash_prefetch(smF, 1, 0, kp, vtp, tid);
    cp_commit();
    if (niter > 1) flash_prefetch(smF, 2, 1, kp, vtp, tid);
    cp_commit();

    cp_wait<2>();
    __syncthreads();

    uint32_t qf[8][4];
    {
        const int swq = g << 3;
#pragma unroll
        for (int c = 0; c < 8; c++) {
            int wb = (c * 8 + 2 * t) ^ swq;
            uint2 a0 = *(const uint2*)&smF[rowbase * FKW + wb];
            uint2 a1 = *(const uint2*)&smF[(rowbase + 8) * FKW + wb];
            qf[c][0] = a0.x; qf[c][2] = a0.y;
            qf[c][1] = a1.x; qf[c][3] = a1.y;
        }
    }
    __syncthreads();

    const int kend0 = kend_of(q0 + rowbase);
    const int kend1 = kend_of(q0 + rowbase + 8);

    float m0v = -1e30f, m1v = -1e30f, l0v = 0.f, l1v = 0.f;
    float O[16][4];
#pragma unroll
    for (int j = 0; j < 16; j++)
#pragma unroll
        for (int c = 0; c < 4; c++) O[j][c] = 0.f;

    for (int it = 0; it < niter; it++) {
        const int k0 = it * 64;
        if (it + 1 >= niter) cp_wait<0>(); else cp_wait<1>();
        __syncthreads();
        if (it + 2 < niter) {
            flash_prefetch(smF, it % 3, it + 2, kp, vtp, tid);
            cp_commit();
        }

        uint32_t* Kb = smF + ((it + 1) % 3) * FSTG;
        uint32_t* Vt = Kb + KTILE;

        float sc[8][4];
#pragma unroll
        for (int j = 0; j < 8; j++)
#pragma unroll
            for (int c = 0; c < 4; c++) sc[j][c] = 0.f;

        const int swk = g << 3;
#pragma unroll
        for (int c = 0; c < 8; c++) {
            int wb = (c * 8 + 2 * t) ^ swk;
#pragma unroll
            for (int j = 0; j < 8; j++) {
                uint2 bb = *(const uint2*)&Kb[(8 * j + g) * FKW + wb];
                mma16f(sc[j], qf[c][0], qf[c][1], qf[c][2], qf[c][3], bb.x, bb.y);
            }
        }

        float rmax0 = -1e30f, rmax1 = -1e30f;
#pragma unroll
        for (int j = 0; j < 8; j++) {
            int c0 = k0 + 8 * j + 2 * t, c1 = c0 + 1;
            if (c0 >= kend0) sc[j][0] = -1e30f;
            if (c1 >= kend0) sc[j][1] = -1e30f;
            if (c0 >= kend1) sc[j][2] = -1e30f;
            if (c1 >= kend1) sc[j][3] = -1e30f;
            rmax0 = fmaxf(rmax0, fmaxf(sc[j][0], sc[j][1]));
            rmax1 = fmaxf(rmax1, fmaxf(sc[j][2], sc[j][3]));
        }
        rmax0 = fmaxf(rmax0, __shfl_xor_sync(0xffffffffu, rmax0, 1));
        rmax0 = fmaxf(rmax0, __shfl_xor_sync(0xffffffffu, rmax0, 2));
        rmax1 = fmaxf(rmax1, __shfl_xor_sync(0xffffffffu, rmax1, 1));
        rmax1 = fmaxf(rmax1, __shfl_xor_sync(0xffffffffu, rmax1, 2));

        float mn0 = fmaxf(m0v, rmax0), mn1 = fmaxf(m1v, rmax1);
        float al0 = __expf(m0v - mn0), al1 = __expf(m1v - mn1);
        float rs0 = 0.f, rs1 = 0.f;
#pragma unroll
        for (int j = 0; j < 8; j++) {
            float p0 = (sc[j][0] > -5e29f) ? __expf(sc[j][0] - mn0) : 0.f;
            float p1 = (sc[j][1] > -5e29f) ? __expf(sc[j][1] - mn0) : 0.f;
            float p2 = (sc[j][2] > -5e29f) ? __expf(sc[j][2] - mn1) : 0.f;
            float p3 = (sc[j][3] > -5e29f) ? __expf(sc[j][3] - mn1) : 0.f;
            rs0 += p0 + p1;
            rs1 += p2 + p3;
            sc[j][0] = p0; sc[j][1] = p1; sc[j][2] = p2; sc[j][3] = p3;
        }
        rs0 += __shfl_xor_sync(0xffffffffu, rs0, 1);
        rs0 += __shfl_xor_sync(0xffffffffu, rs0, 2);
        rs1 += __shfl_xor_sync(0xffffffffu, rs1, 1);
        rs1 += __shfl_xor_sync(0xffffffffu, rs1, 2);
        l0v = l0v * al0 + rs0;
        l1v = l1v * al1 + rs1;
        m0v = mn0; m1v = mn1;

#pragma unroll
        for (int j = 0; j < 16; j++) {
            O[j][0] *= al0; O[j][1] *= al0;
            O[j][2] *= al1; O[j][3] *= al1;
        }

        const int swv = g << 2;
#pragma unroll
        for (int c = 0; c < 4; c++) {
            uint32_t a0 = pack_h2(sc[2 * c][0],     sc[2 * c][1]);
            uint32_t a1 = pack_h2(sc[2 * c][2],     sc[2 * c][3]);
            uint32_t a2 = pack_h2(sc[2 * c + 1][0], sc[2 * c + 1][1]);
            uint32_t a3 = pack_h2(sc[2 * c + 1][2], sc[2 * c + 1][3]);
            int wv = (c * 8 + 2 * t) ^ swv;
#pragma unroll
            for (int j = 0; j < 16; j++) {
                uint2 bb = *(const uint2*)&Vt[(8 * j + g) * FVW + wv];
                mma16f(O[j], a0, a1, a2, a3, bb.x, bb.y);
            }
        }
    }

    // epilogue: normalize, single fp16 pair store (pair-permuted)
    const int b = bh >> 4;
    const int h = bh & 15;
#pragma unroll
    for (int rr = 0; rr < 2; rr++) {
        int lq = q0 + rowbase + 8 * rr;
        if (lq >= L_) continue;
        float inv = 1.f / (rr ? l1v : l0v);
        size_t rowoff = (size_t)(b * L_ + lq) * KP_;
#pragma unroll
        for (int j = 0; j < 16; j++) {
            float x0 = O[j][2 * rr] * inv;
            float x1 = O[j][2 * rr + 1] * inv;
            int p = h * 64 + 4 * j + t;
            g_aof[rowoff + pair_perm(p)] = pack_h2(x0, x1);
        }
    }
}

// ---------------------------------------------------------------------------
// launch
// ---------------------------------------------------------------------------
extern "C" void kernel_launch(void* const* d_in, const int* in_sizes, int n_in,
                              void* d_out, int out_size)
{
    const float* x    = (const float*)d_in[0];
    const float* Wqkv = (const float*)d_in[1];
    const float* qb   = (const float*)d_in[2];
    const float* vb   = (const float*)d_in[3];
    const float* sml  = (const float*)d_in[4];
    const float* pW   = (const float*)d_in[5];
    const float* pb   = (const float*)d_in[6];
    const float* rope = (const float*)d_in[7];
    float* out = (float*)d_out;

    const size_t gemm_shm  = (size_t)3 * QSTG * sizeof(uint32_t);     // 49,152 B
    const size_t flash_shm = (size_t)3 * FSTG * sizeof(uint32_t);     // 98,304 B

    cudaFuncSetAttribute(qkv_gemm, cudaFuncAttributeMaxDynamicSharedMemorySize, (int)gemm_shm);
    cudaFuncSetAttribute(proj_gemm, cudaFuncAttributeMaxDynamicSharedMemorySize, (int)gemm_shm);
    cudaFuncSetAttribute(flash_attn, cudaFuncAttributeMaxDynamicSharedMemorySize, (int)flash_shm);

    {
        int np;
        np = M_ * KP_;    convert_f16<<<(np + 255) / 256, 256>>>(x, 0, np);
        np = NQKV * KP_;  convert_f16<<<(np + 255) / 256, 256>>>(Wqkv, 1, np);
        np = C_ * KP_;    convert_f16<<<(np + 255) / 256, 256>>>(pW, 2, np);
    }

    dim3 g1(NQKV / 128, (M_ + 127) / 128);   // 48 x 40
    qkv_gemm<<<g1, 256, gemm_shm>>>(qb, vb);

    int nwarps = B_ * H_ * L_;
    norm_rope<<<(nwarps + 7) / 8, 256>>>(sml, rope);

    {
        int nth = B_ * H_ * VL2 * HD_;
        vt_transpose<<<(nth + 255) / 256, 256>>>();
    }

    dim3 g3((L_ + 127) / 128, B_ * H_);      // 20 x 32
    flash_attn<<<g3, 256, flash_shm>>>();

    dim3 g4(C_ / 128, (M_ + 127) / 128);     // 16 x 40
    proj_gemm<<<g4, 256, gemm_shm>>>(pb, out);
}

// round 16
// speedup vs baseline: 3.4616x; 1.0141x over previous
#include <cuda_runtime.h>
#include <cuda_bf16.h>
#include <cuda_fp16.h>
#include <cstdint>
#include <math.h>

// ---------------------------------------------------------------------------
// Problem constants
// ---------------------------------------------------------------------------
#define B_   2
#define L_   2521
#define C_   2048
#define H_   16
#define HD_  128
#define M_   (B_ * L_)          // 5042
#define K_   2048
#define KP_  1024               // K/2 u32 pairs per row
#define NQKV 6144
#define VL2  1280               // padded key-pairs per (bh, d) row of g_vt

__device__ __constant__ int d_cum[10] = {1, 5, 21, 57, 121, 265, 521, 921, 1497, 2521};

// f32 scratch (plain d-order)
__device__ float g_q[B_ * H_ * L_ * HD_];
__device__ float g_k[B_ * H_ * L_ * HD_];
__device__ float g_v[B_ * H_ * L_ * HD_];

// fp16 operands (u32 = packed half2)
__device__ uint32_t g_xf[M_ * KP_];          // x         (qkv A, perm4)
__device__ uint32_t g_wf[NQKV * KP_];        // W_qkv     (qkv B, perm4)
__device__ uint32_t g_qh[B_ * H_ * L_ * 64]; // q         (flash A, perm2)
__device__ uint32_t g_kh[B_ * H_ * L_ * 64]; // k         (flash S-B, perm2)
__device__ uint32_t g_vt[(size_t)B_ * H_ * HD_ * VL2]; // V^T (flash PV-B, perm2)
__device__ uint32_t g_aof[M_ * KP_];         // attn out  (proj A, perm4)
__device__ uint32_t g_pwf[C_ * KP_];         // proj_W    (proj B, perm4)

// ---------------------------------------------------------------------------
// helpers
// ---------------------------------------------------------------------------
__device__ __forceinline__ uint32_t pack_h2(float lo, float hi) {
    uint32_t r;
    asm("cvt.rn.f16x2.f32 %0, %1, %2;" : "=r"(r) : "f"(hi), "f"(lo));
    return r;
}

__device__ __forceinline__ void mma16f(float* c,
                                       uint32_t a0, uint32_t a1, uint32_t a2, uint32_t a3,
                                       uint32_t b0, uint32_t b1)
{
    asm volatile(
        "mma.sync.aligned.m16n8k16.row.col.f32.f16.f16.f32 "
        "{%0,%1,%2,%3}, {%4,%5,%6,%7}, {%8,%9}, {%0,%1,%2,%3};"
        : "+f"(c[0]), "+f"(c[1]), "+f"(c[2]), "+f"(c[3])
        : "r"(a0), "r"(a1), "r"(a2), "r"(a3), "r"(b0), "r"(b1));
}

__device__ __forceinline__ uint32_t smaddr(const void* p) {
    return (uint32_t)__cvta_generic_to_shared(p);
}
__device__ __forceinline__ void cp16(uint32_t dst, const void* src, bool pred) {
    int sz = pred ? 16 : 0;
    asm volatile("cp.async.cg.shared.global [%0], [%1], 16, %2;"
                 :: "r"(dst), "l"(src), "r"(sz));
}
__device__ __forceinline__ void cp_commit() {
    asm volatile("cp.async.commit_group;");
}
template<int N>
__device__ __forceinline__ void cp_wait() {
    asm volatile("cp.async.wait_group %0;" :: "n"(N));
}

// perm2: flash layout — pair (t, t+4) of chunk c -> words c*8 + {2t, 2t+1}
__device__ __forceinline__ int pair_perm(int p) {
    int q = p & 15;
    return (p & ~15) + (q & 8) + (q & 3) * 2 + ((q >> 2) & 1);
}
// perm4: GEMM layout — word = t*4 + chunk*2 + hi  (uint4 = frags of BOTH chunks)
__device__ __forceinline__ int perm4(int p) {
    int q = p & 15;
    return (p & ~15) + (q & 3) * 4 + ((q >> 3) & 1) * 2 + ((q >> 2) & 1);
}

// ---------------------------------------------------------------------------
// Kernel 0: f32 -> fp16 pack, perm4 layout (which: 0=g_xf, 1=g_wf, 2=g_pwf)
// ---------------------------------------------------------------------------
__global__ void __launch_bounds__(256)
convert_f16(const float* __restrict__ src, int which, int npairs)
{
    int i = blockIdx.x * 256 + threadIdx.x;
    if (i >= npairs) return;
    int row = i >> 10;
    int p = i & 1023;
    float2 v = *(const float2*)(src + (size_t)row * K_ + p * 2);
    uint32_t hp = pack_h2(v.x, v.y);
    uint32_t* dst = (which == 0) ? g_xf : (which == 1) ? g_wf : g_pwf;
    dst[(size_t)row * KP_ + perm4(p)] = hp;
}

// ---------------------------------------------------------------------------
// Kernel 0c: tiled V transpose -> g_vt[bh][d][key pair slot] (perm2),
// coalesced 128B gmem stores (warp-per-d-row).
// ---------------------------------------------------------------------------
__global__ void __launch_bounds__(256)
vt_transpose()
{
    __shared__ float tile[64][132];
    const int kb = blockIdx.x;       // key block: keys [kb*64, kb*64+64)
    const int bh = blockIdx.y;
    const int tid = threadIdx.x;
    const int wid = tid >> 5, lane = tid & 31;

    {
        int r = tid >> 2;                 // 0..63
        int cb = (tid & 3) * 32;
        int key = kb * 64 + r;
        bool ok = key < L_;
        const float* src = g_v + ((size_t)bh * L_ + (ok ? key : 0)) * HD_ + cb;
#pragma unroll
        for (int i = 0; i < 8; i++) {
            float4 v = ok ? *(const float4*)(src + 4 * i)
                          : make_float4(0.f, 0.f, 0.f, 0.f);
            *(float4*)&tile[r][cb + 4 * i] = v;
        }
    }
    __syncthreads();

#pragma unroll
    for (int it = 0; it < 16; it++) {
        int d = wid * 16 + it;
        float f0 = tile[2 * lane][d];
        float f1 = tile[2 * lane + 1][d];
        int gp = kb * 32 + lane;
        g_vt[((size_t)bh * HD_ + d) * VL2 + pair_perm(gp)] = pack_h2(f0, f1);
    }
}

// ---------------------------------------------------------------------------
// Single-term fp16 GEMM mainloop (qkv & proj): C[128x128]=A*B^T, BK=32,
// 3-stage cp.async, XOR swizzle, uint4 fragment loads (both k16 chunks).
// ---------------------------------------------------------------------------
#define GW 16
#define QARR (128 * GW)
#define QSTG (2 * QARR)

__device__ __forceinline__ void f16_prefetch(
    uint32_t* sbase, const uint32_t* ag, const uint32_t* bg,
    int ku, bool aok, int r, int fq)
{
    int sw = (r & 3) << 2;
    int w0 = (fq ^ sw) * 4;
    int w1 = ((fq + 4) ^ sw) * 4;
    uint32_t dA = smaddr(sbase + r * GW);
    cp16(dA + w0, ag + ku,     aok);
    cp16(dA + w1, ag + ku + 4, aok);
    uint32_t dB = dA + QARR * 4;
    cp16(dB + w0, bg + ku,     true);
    cp16(dB + w1, bg + ku + 4, true);
}

__device__ __forceinline__ void f16_core(
    const uint32_t* __restrict__ Ag, const uint32_t* __restrict__ Bg,
    int m0, int n0, uint32_t* smu, float acc[2][8][4], int tid)
{
    const int lane = tid & 31, wid = tid >> 5;
    const int g = lane >> 2, t = lane & 3;
    const int mw = (wid >> 1) * 32, nw = (wid & 1) * 64;

    const int r = tid >> 1;
    const int fq = (tid & 1) * 8;
    const bool aok = (m0 + r) < M_;
    const uint32_t* ag = Ag + (size_t)(aok ? m0 + r : 0) * KP_ + fq;
    const uint32_t* bg = Bg + (size_t)(n0 + r) * KP_ + fq;

    f16_prefetch(smu,            ag, bg, 0,  aok, r, fq);
    cp_commit();
    f16_prefetch(smu + QSTG,     ag, bg, 16, aok, r, fq);
    cp_commit();

    const int wb4 = (4 * t) ^ ((g & 3) << 2);
    const int NIT = KP_ / 16;

    for (int it = 0; it < NIT; it++) {
        if (it + 1 >= NIT) cp_wait<0>(); else cp_wait<1>();
        __syncthreads();
        if (it + 2 < NIT) {
            f16_prefetch(smu + ((it + 2) % 3) * QSTG, ag, bg, (it + 2) * 16, aok, r, fq);
            cp_commit();
        }

        uint32_t* As = smu + (it % 3) * QSTG;
        uint32_t* Bs = As + QARR;

        // A fragments for both chunks via uint4
        uint4 va0[2], va1[2];
#pragma unroll
        for (int mi = 0; mi < 2; mi++) {
            int r0 = mw + 16 * mi + g;
            va0[mi] = *(const uint4*)&As[r0 * GW + wb4];
            va1[mi] = *(const uint4*)&As[(r0 + 8) * GW + wb4];
        }
#pragma unroll
        for (int j = 0; j < 8; j++) {
            int cn = nw + 8 * j + g;
            uint4 bb = *(const uint4*)&Bs[cn * GW + wb4];
#pragma unroll
            for (int mi = 0; mi < 2; mi++) {
                // chunk 0
                mma16f(acc[mi][j], va0[mi].x, va1[mi].x, va0[mi].y, va1[mi].y, bb.x, bb.y);
                // chunk 1
                mma16f(acc[mi][j], va0[mi].z, va1[mi].z, va0[mi].w, va1[mi].w, bb.z, bb.w);
            }
        }
    }
}

// ---------------------------------------------------------------------------
// Kernel 1: QKV GEMM + scatter epilogue (plain f32 q/k/v)
// ---------------------------------------------------------------------------
__global__ void __launch_bounds__(256, 2)
qkv_gemm(const float* __restrict__ qb, const float* __restrict__ vb)
{
    extern __shared__ uint32_t smu[];
    float acc[2][8][4];
#pragma unroll
    for (int a = 0; a < 2; a++)
#pragma unroll
        for (int b = 0; b < 8; b++)
#pragma unroll
            for (int c = 0; c < 4; c++) acc[a][b][c] = 0.f;

    const int tid = threadIdx.x;
    const int lane = tid & 31, wid = tid >> 5;
    const int g = lane >> 2, t = lane & 3;
    const int mw = (wid >> 1) * 32, nw = (wid & 1) * 64;
    const int n0 = blockIdx.x * 128;
    const int m0 = blockIdx.y * 128;

    f16_core(g_xf, g_wf, m0, n0, smu, acc, tid);

    const int tq = n0 >> 11;
    const int h = (n0 & 2047) >> 7;
    float* dst = (tq == 0) ? g_q : ((tq == 1) ? g_k : g_v);

    float2 bias[8];
#pragma unroll
    for (int j = 0; j < 8; j++) {
        int d = nw + 8 * j + 2 * t;
        float b0 = 0.f, b1 = 0.f;
        if (tq == 0) { b0 = qb[h * HD_ + d]; b1 = qb[h * HD_ + d + 1]; }
        else if (tq == 2) { b0 = vb[h * HD_ + d]; b1 = vb[h * HD_ + d + 1]; }
        bias[j] = make_float2(b0, b1);
    }

#pragma unroll
    for (int mi = 0; mi < 2; mi++)
#pragma unroll
        for (int rr = 0; rr < 2; rr++) {
            int gm = m0 + mw + 16 * mi + g + 8 * rr;
            if (gm >= M_) continue;
            int b = gm / L_;
            int l = gm - b * L_;
            float* p = dst + ((size_t)(b * H_ + h) * L_ + l) * HD_;
#pragma unroll
            for (int j = 0; j < 8; j++) {
                float2 o;
                o.x = acc[mi][j][2 * rr] + bias[j].x;
                o.y = acc[mi][j][2 * rr + 1] + bias[j].y;
                *(float2*)(p + nw + 8 * j + 2 * t) = o;
            }
        }
}

// ---------------------------------------------------------------------------
// Kernel 4: proj GEMM (single-term fp16) + bias epilogue
// ---------------------------------------------------------------------------
__global__ void __launch_bounds__(256, 2)
proj_gemm(const float* __restrict__ pb, float* __restrict__ out)
{
    extern __shared__ uint32_t smu[];
    float acc[2][8][4];
#pragma unroll
    for (int a = 0; a < 2; a++)
#pragma unroll
        for (int b = 0; b < 8; b++)
#pragma unroll
            for (int c = 0; c < 4; c++) acc[a][b][c] = 0.f;

    const int tid = threadIdx.x;
    const int lane = tid & 31, wid = tid >> 5;
    const int g = lane >> 2, t = lane & 3;
    const int mw = (wid >> 1) * 32, nw = (wid & 1) * 64;
    const int n0 = blockIdx.x * 128;
    const int m0 = blockIdx.y * 128;

    f16_core(g_aof, g_pwf, m0, n0, smu, acc, tid);

    float2 bias[8];
#pragma unroll
    for (int j = 0; j < 8; j++) {
        int n = n0 + nw + 8 * j + 2 * t;
        bias[j] = make_float2(pb[n], pb[n + 1]);
    }

#pragma unroll
    for (int mi = 0; mi < 2; mi++)
#pragma unroll
        for (int rr = 0; rr < 2; rr++) {
            int gm = m0 + mw + 16 * mi + g + 8 * rr;
            if (gm >= M_) continue;
            float* p = out + (size_t)gm * C_ + n0 + nw;
#pragma unroll
            for (int j = 0; j < 8; j++) {
                float2 o;
                o.x = acc[mi][j][2 * rr] + bias[j].x;
                o.y = acc[mi][j][2 * rr + 1] + bias[j].y;
                *(float2*)(p + 8 * j + 2 * t) = o;
            }
        }
}

// ---------------------------------------------------------------------------
// Kernel 2: norm + rope; writes fp16 perm2 q/k (flash operands)
// ---------------------------------------------------------------------------
__global__ void __launch_bounds__(256)
norm_rope(const float* __restrict__ sml, const float* __restrict__ rope)
{
    const int gw = blockIdx.x * 8 + (threadIdx.x >> 5);
    const int lane = threadIdx.x & 31;
    if (gw >= B_ * H_ * L_) return;
    const int l = gw % L_;
    const int h = (gw / L_) % H_;

    float2 cc = *(const float2*)(rope + (size_t)l * 64 + lane * 2);
    float2 ss = *(const float2*)(rope + (size_t)L_ * 64 + (size_t)l * 64 + lane * 2);
    const float scale = __expf(fminf(sml[h], 4.605170185988091f));
    const size_t base = (size_t)gw * HD_ + lane * 4;
    const int s0 = pair_perm(2 * lane);
    const int s1 = pair_perm(2 * lane + 1);

    {
        float4 v = *(const float4*)(g_q + base);
        float ssq = v.x * v.x + v.y * v.y + v.z * v.z + v.w * v.w;
#pragma unroll
        for (int o = 16; o; o >>= 1) ssq += __shfl_xor_sync(0xffffffffu, ssq, o);
        float inv = scale / fmaxf(sqrtf(ssq), 1e-12f);
        v.x *= inv; v.y *= inv; v.z *= inv; v.w *= inv;
        float rx = cc.x * v.x - ss.x * v.y;
        float ry = ss.x * v.x + cc.x * v.y;
        float rz = cc.y * v.z - ss.y * v.w;
        float rw = ss.y * v.z + cc.y * v.w;
        g_qh[(size_t)gw * 64 + s0] = pack_h2(rx, ry);
        g_qh[(size_t)gw * 64 + s1] = pack_h2(rz, rw);
    }
    {
        float4 v = *(const float4*)(g_k + base);
        float ssq = v.x * v.x + v.y * v.y + v.z * v.z + v.w * v.w;
#pragma unroll
        for (int o = 16; o; o >>= 1) ssq += __shfl_xor_sync(0xffffffffu, ssq, o);
        float inv = 1.f / fmaxf(sqrtf(ssq), 1e-12f);
        v.x *= inv; v.y *= inv; v.z *= inv; v.w *= inv;
        float rx = cc.x * v.x - ss.x * v.y;
        float ry = ss.x * v.x + cc.x * v.y;
        float rz = cc.y * v.z - ss.y * v.w;
        float rw = ss.y * v.z + cc.y * v.w;
        g_kh[(size_t)gw * 64 + s0] = pack_h2(rx, ry);
        g_kh[(size_t)gw * 64 + s1] = pack_h2(rz, rw);
    }
}

// ---------------------------------------------------------------------------
// Kernel 3: flash attention, all-fp16 mma (R15 version; epilogue uses perm4)
// ---------------------------------------------------------------------------
#define FKW 64
#define FVW 32
#define KTILE (64 * FKW)
#define VTILE (128 * FVW)
#define FSTG (KTILE + VTILE)

__device__ __forceinline__ int kend_of(int lq) {
    if (lq >= L_) return 0;
    int ke = 2521;
#pragma unroll
    for (int i = 9; i >= 0; i--)
        if (lq < d_cum[i]) ke = d_cum[i];
    return ke;
}

__device__ __forceinline__ void flash_prefetch(
    uint32_t* sm, int s, int it, const uint32_t* kp, const uint32_t* vtp, int tid)
{
    uint32_t* Kb = sm + s * FSTG;
    uint32_t* Vb = Kb + KTILE;
    const int k0 = it * 64;
    {
        int kr = tid >> 2;
        int cb = (tid & 3) * 16;
        bool ok = (k0 + kr) < L_;
        const uint32_t* src = kp + (size_t)(ok ? (k0 + kr) : 0) * 64 + cb;
        int sw = (kr & 7) << 3;
        uint32_t d = smaddr(Kb + kr * FKW);
#pragma unroll
        for (int i = 0; i < 4; i++)
            cp16(d + 4 * ((cb + 4 * i) ^ sw), src + 4 * i, ok);
    }
    {
        int dr = tid >> 1;
        int cb = (tid & 1) * 16;
        const uint32_t* src = vtp + (size_t)dr * VL2 + it * 32 + cb;
        int sw = (dr & 7) << 2;
        uint32_t d = smaddr(Vb + dr * FVW);
#pragma unroll
        for (int i = 0; i < 4; i++)
            cp16(d + 4 * ((cb + 4 * i) ^ sw), src + 4 * i, true);
    }
}

__global__ void __launch_bounds__(256, 1)
flash_attn()
{
    extern __shared__ uint32_t smF[];

    const int bh = blockIdx.y;
    const int q0 = (gridDim.x - 1 - blockIdx.x) * 128;
    const uint32_t* qp = g_qh + (size_t)bh * L_ * 64;
    const uint32_t* kp = g_kh + (size_t)bh * L_ * 64;
    const uint32_t* vtp = g_vt + (size_t)bh * HD_ * VL2;
    const int tid = threadIdx.x, lane = tid & 31, wid = tid >> 5;
    const int g = lane >> 2, t = lane & 3;
    const int rowbase = wid * 16 + g;

    int kmax;
    {
        int lql = min(q0 + 127, L_ - 1);
        kmax = 2521;
#pragma unroll
        for (int i = 9; i >= 0; i--)
            if (lql < d_cum[i]) kmax = d_cum[i];
    }
    const int niter = (kmax + 63) / 64;

    {
        int r = tid >> 1;
        int cb = (tid & 1) * 32;
        bool ok = (q0 + r) < L_;
        const uint32_t* src = qp + (size_t)(ok ? (q0 + r) : 0) * 64 + cb;
        int sw = (r & 7) << 3;
        uint32_t d = smaddr(smF + r * FKW);
#pragma unroll
        for (int i = 0; i < 8; i++)
            cp16(d + 4 * ((cb + 4 * i) ^ sw), src + 4 * i, ok);
    }
    cp_commit();
    flash_prefetch(smF, 1, 0, kp, vtp, tid);
    cp_commit();
    if (niter > 1) flash_prefetch(smF, 2, 1, kp, vtp, tid);
    cp_commit();

    cp_wait<2>();
    __syncthreads();

    uint32_t qf[8][4];
    {
        const int swq = g << 3;
#pragma unroll
        for (int c = 0; c < 8; c++) {
            int wb = (c * 8 + 2 * t) ^ swq;
            uint2 a0 = *(const uint2*)&smF[rowbase * FKW + wb];
            uint2 a1 = *(const uint2*)&smF[(rowbase + 8) * FKW + wb];
            qf[c][0] = a0.x; qf[c][2] = a0.y;
            qf[c][1] = a1.x; qf[c][3] = a1.y;
        }
    }
    __syncthreads();

    const int kend0 = kend_of(q0 + rowbase);
    const int kend1 = kend_of(q0 + rowbase + 8);

    float m0v = -1e30f, m1v = -1e30f, l0v = 0.f, l1v = 0.f;
    float O[16][4];
#pragma unroll
    for (int j = 0; j < 16; j++)
#pragma unroll
        for (int c = 0; c < 4; c++) O[j][c] = 0.f;

    for (int it = 0; it < niter; it++) {
        const int k0 = it * 64;
        if (it + 1 >= niter) cp_wait<0>(); else cp_wait<1>();
        __syncthreads();
        if (it + 2 < niter) {
            flash_prefetch(smF, it % 3, it + 2, kp, vtp, tid);
            cp_commit();
        }

        uint32_t* Kb = smF + ((it + 1) % 3) * FSTG;
        uint32_t* Vt = Kb + KTILE;

        float sc[8][4];
#pragma unroll
        for (int j = 0; j < 8; j++)
#pragma unroll
            for (int c = 0; c < 4; c++) sc[j][c] = 0.f;

        const int swk = g << 3;
#pragma unroll
        for (int c = 0; c < 8; c++) {
            int wb = (c * 8 + 2 * t) ^ swk;
#pragma unroll
            for (int j = 0; j < 8; j++) {
                uint2 bb = *(const uint2*)&Kb[(8 * j + g) * FKW + wb];
                mma16f(sc[j], qf[c][0], qf[c][1], qf[c][2], qf[c][3], bb.x, bb.y);
            }
        }

        float rmax0 = -1e30f, rmax1 = -1e30f;
#pragma unroll
        for (int j = 0; j < 8; j++) {
            int c0 = k0 + 8 * j + 2 * t, c1 = c0 + 1;
            if (c0 >= kend0) sc[j][0] = -1e30f;
            if (c1 >= kend0) sc[j][1] = -1e30f;
            if (c0 >= kend1) sc[j][2] = -1e30f;
            if (c1 >= kend1) sc[j][3] = -1e30f;
            rmax0 = fmaxf(rmax0, fmaxf(sc[j][0], sc[j][1]));
            rmax1 = fmaxf(rmax1, fmaxf(sc[j][2], sc[j][3]));
        }
        rmax0 = fmaxf(rmax0, __shfl_xor_sync(0xffffffffu, rmax0, 1));
        rmax0 = fmaxf(rmax0, __shfl_xor_sync(0xffffffffu, rmax0, 2));
        rmax1 = fmaxf(rmax1, __shfl_xor_sync(0xffffffffu, rmax1, 1));
        rmax1 = fmaxf(rmax1, __shfl_xor_sync(0xffffffffu, rmax1, 2));

        float mn0 = fmaxf(m0v, rmax0), mn1 = fmaxf(m1v, rmax1);
        float al0 = __expf(m0v - mn0), al1 = __expf(m1v - mn1);
        float rs0 = 0.f, rs1 = 0.f;
#pragma unroll
        for (int j = 0; j < 8; j++) {
            float p0 = (sc[j][0] > -5e29f) ? __expf(sc[j][0] - mn0) : 0.f;
            float p1 = (sc[j][1] > -5e29f) ? __expf(sc[j][1] - mn0) : 0.f;
            float p2 = (sc[j][2] > -5e29f) ? __expf(sc[j][2] - mn1) : 0.f;
            float p3 = (sc[j][3] > -5e29f) ? __expf(sc[j][3] - mn1) : 0.f;
            rs0 += p0 + p1;
            rs1 += p2 + p3;
            sc[j][0] = p0; sc[j][1] = p1; sc[j][2] = p2; sc[j][3] = p3;
        }
        rs0 += __shfl_xor_sync(0xffffffffu, rs0, 1);
        rs0 += __shfl_xor_sync(0xffffffffu, rs0, 2);
        rs1 += __shfl_xor_sync(0xffffffffu, rs1, 1);
        rs1 += __shfl_xor_sync(0xffffffffu, rs1, 2);
        l0v = l0v * al0 + rs0;
        l1v = l1v * al1 + rs1;
        m0v = mn0; m1v = mn1;

#pragma unroll
        for (int j = 0; j < 16; j++) {
            O[j][0] *= al0; O[j][1] *= al0;
            O[j][2] *= al1; O[j][3] *= al1;
        }

        const int swv = g << 2;
#pragma unroll
        for (int c = 0; c < 4; c++) {
            uint32_t a0 = pack_h2(sc[2 * c][0],     sc[2 * c][1]);
            uint32_t a1 = pack_h2(sc[2 * c][2],     sc[2 * c][3]);
            uint32_t a2 = pack_h2(sc[2 * c + 1][0], sc[2 * c + 1][1]);
            uint32_t a3 = pack_h2(sc[2 * c + 1][2], sc[2 * c + 1][3]);
            int wv = (c * 8 + 2 * t) ^ swv;
#pragma unroll
            for (int j = 0; j < 16; j++) {
                uint2 bb = *(const uint2*)&Vt[(8 * j + g) * FVW + wv];
                mma16f(O[j], a0, a1, a2, a3, bb.x, bb.y);
            }
        }
    }

    // epilogue: normalize, single fp16 pair store (perm4 layout for proj)
    const int b = bh >> 4;
    const int h = bh & 15;
#pragma unroll
    for (int rr = 0; rr < 2; rr++) {
        int lq = q0 + rowbase + 8 * rr;
        if (lq >= L_) continue;
        float inv = 1.f / (rr ? l1v : l0v);
        size_t rowoff = (size_t)(b * L_ + lq) * KP_;
#pragma unroll
        for (int j = 0; j < 16; j++) {
            float x0 = O[j][2 * rr] * inv;
            float x1 = O[j][2 * rr + 1] * inv;
            int p = h * 64 + 4 * j + t;
            g_aof[rowoff + perm4(p)] = pack_h2(x0, x1);
        }
    }
}

// ---------------------------------------------------------------------------
// launch
// ---------------------------------------------------------------------------
extern "C" void kernel_launch(void* const* d_in, const int* in_sizes, int n_in,
                              void* d_out, int out_size)
{
    const float* x    = (const float*)d_in[0];
    const float* Wqkv = (const float*)d_in[1];
    const float* qb   = (const float*)d_in[2];
    const float* vb   = (const float*)d_in[3];
    const float* sml  = (const float*)d_in[4];
    const float* pW   = (const float*)d_in[5];
    const float* pb   = (const float*)d_in[6];
    const float* rope = (const float*)d_in[7];
    float* out = (float*)d_out;

    const size_t gemm_shm  = (size_t)3 * QSTG * sizeof(uint32_t);     // 49,152 B
    const size_t flash_shm = (size_t)3 * FSTG * sizeof(uint32_t);     // 98,304 B

    cudaFuncSetAttribute(qkv_gemm, cudaFuncAttributeMaxDynamicSharedMemorySize, (int)gemm_shm);
    cudaFuncSetAttribute(proj_gemm, cudaFuncAttributeMaxDynamicSharedMemorySize, (int)gemm_shm);
    cudaFuncSetAttribute(flash_attn, cudaFuncAttributeMaxDynamicSharedMemorySize, (int)flash_shm);

    {
        int np;
        np = M_ * KP_;    convert_f16<<<(np + 255) / 256, 256>>>(x, 0, np);
        np = NQKV * KP_;  convert_f16<<<(np + 255) / 256, 256>>>(Wqkv, 1, np);
        np = C_ * KP_;    convert_f16<<<(np + 255) / 256, 256>>>(pW, 2, np);
    }

    dim3 g1(NQKV / 128, (M_ + 127) / 128);   // 48 x 40
    qkv_gemm<<<g1, 256, gemm_shm>>>(qb, vb);

    int nwarps = B_ * H_ * L_;
    norm_rope<<<(nwarps + 7) / 8, 256>>>(sml, rope);

    {
        dim3 gv(40, B_ * H_);                // 40 key-blocks x 32 bh
        vt_transpose<<<gv, 256>>>();
    }

    dim3 g3((L_ + 127) / 128, B_ * H_);      // 20 x 32
    flash_attn<<<g3, 256, flash_shm>>>();

    dim3 g4(C_ / 128, (M_ + 127) / 128);     // 16 x 40
    proj_gemm<<<g4, 256, gemm_shm>>>(pb, out);
}